// round 14
// baseline (speedup 1.0000x reference)
#include <cuda_runtime.h>
#include <cuda_fp16.h>
#include <cstdint>
#include <math.h>

// Problem dims (fixed)
#define Bb 4
#define Ss 2048
#define Ee 512
#define Hh 1024
#define BS (Bb*Ss)
#define BE (Bb*Ee)

// fp32 scratch
__device__ float g_q [BS*Hh];
__device__ float g_kt[BS*Hh];
__device__ float g_vt[BS*Hh];
__device__ float g_ve[BE*Hh];
__device__ float g_sc[(size_t)BS*512];       // raw ext scores
__device__ float g_s0[BS];                   // self score / prob
// Fragment-major (hi,lo separated) scratch.
// A-frag: per (k16,m16) block: 32 x uint4 hi, 32 x uint4 lo (1024 B)
// B-frag: per (k16,n8)  block: 32 x uint2 hi, 32 x uint2 lo (512 B)
__device__ __align__(16) uint4 g_hsF[(size_t)BS*Hh/4];
__device__ __align__(16) uint4 g_exF[(size_t)BE*Hh/4];
__device__ __align__(16) uint4 g_qF [(size_t)BS*Hh/4];
__device__ __align__(16) uint4 g_pF [(size_t)BS*512/4];
__device__ __align__(16) uint2 g_wF [3*(size_t)Hh*Hh/2];
__device__ __align__(16) uint2 g_keF[(size_t)Hh*BE/2];
__device__ __align__(16) uint2 g_veF[(size_t)BE*Hh/2];

#define WSCALE 32.0f
#define WINV   (1.0f / 32.0f)

__device__ __forceinline__ void split2(float x, float y,
                                       uint32_t &h, uint32_t &l)
{
    asm("cvt.rn.f16x2.f32 %0, %1, %2;" : "=r"(h) : "f"(y), "f"(x));
    __half2 hv = *reinterpret_cast<__half2*>(&h);
    float2 b = __half22float2(hv);
    asm("cvt.rn.f16x2.f32 %0, %1, %2;" : "=r"(l) : "f"(y - b.y), "f"(x - b.x));
}

__device__ __forceinline__ void mma16(float* d, const uint32_t* a,
                                      const uint32_t* b)
{
    asm volatile(
        "mma.sync.aligned.m16n8k16.row.col.f32.f16.f16.f32 "
        "{%0,%1,%2,%3}, {%4,%5,%6,%7}, {%8,%9}, {%0,%1,%2,%3};"
        : "+f"(d[0]), "+f"(d[1]), "+f"(d[2]), "+f"(d[3])
        : "r"(a[0]), "r"(a[1]), "r"(a[2]), "r"(a[3]),
          "r"(b[0]), "r"(b[1]));
}

__device__ __forceinline__ void cpa(uint32_t d, const void* s)
{
    asm volatile("cp.async.cg.shared.global [%0], [%1], 16;"
                 :: "r"(d), "l"(s) : "memory");
}
#define CP_COMMIT() asm volatile("cp.async.commit_group;" ::: "memory")
#define CP_WAIT1()  asm volatile("cp.async.wait_group 1;" ::: "memory")

// ---------------------------------------------------------------------------
// Convert kernels (64x64 fp32 tile staged in smem, then fragment emit)
// ---------------------------------------------------------------------------
#define TILE_LOAD(src, ld, r0, c0)                                            \
    do {                                                                      \
        int r_ = tid >> 2, c4_ = (tid & 3) * 16;                              \
        _Pragma("unroll")                                                     \
        for (int i_ = 0; i_ < 4; i_++) {                                      \
            float4 v_ = *(const float4*)((src) + (size_t)((r0) + r_) * (ld)   \
                                         + (c0) + c4_ + i_ * 4);              \
            t[r_][c4_ + i_*4 + 0] = v_.x;                                     \
            t[r_][c4_ + i_*4 + 1] = v_.y;                                     \
            t[r_][c4_ + i_*4 + 2] = v_.z;                                     \
            t[r_][c4_ + i_*4 + 3] = v_.w;                                     \
        }                                                                     \
    } while (0)

// A-frag from src [M][K] f32. grid (M/64, K/64), 256 thr.
__global__ void conv_A(const float* __restrict__ src, uint4* __restrict__ dst,
                       int M, int K)
{
    __shared__ float t[64][65];
    const int tid = threadIdx.x;
    const int m0 = blockIdx.x * 64, k0 = blockIdx.y * 64;
    TILE_LOAD(src, K, m0, k0);
    __syncthreads();
    #pragma unroll
    for (int j = 0; j < 2; j++) {
        int s = tid + j * 256;
        int kcl = s >> 7, m16l = (s >> 5) & 3, lane = s & 31;
        int gid = lane >> 2, tg = lane & 3;
        int ml = m16l * 16 + gid, kl = kcl * 16 + 2 * tg;
        uint4 h, l;
        split2(t[ml][kl],       t[ml][kl + 1],       h.x, l.x);
        split2(t[ml + 8][kl],   t[ml + 8][kl + 1],   h.y, l.y);
        split2(t[ml][kl + 8],   t[ml][kl + 9],       h.z, l.z);
        split2(t[ml + 8][kl + 8], t[ml + 8][kl + 9], h.w, l.w);
        size_t gb = (size_t)(k0 / 16 + kcl) * (M / 16) + (m0 / 16 + m16l);
        dst[gb * 64 + lane]      = h;
        dst[gb * 64 + 32 + lane] = l;
    }
}

// B-frag from src [K][N] f32 (scaled). grid (N/64, K/64), 256 thr.
__global__ void conv_B(const float* __restrict__ src, uint2* __restrict__ dst,
                       int K, int N, float scale)
{
    __shared__ float t[64][65];
    const int tid = threadIdx.x;
    const int n0 = blockIdx.x * 64, k0 = blockIdx.y * 64;
    TILE_LOAD(src, N, k0, n0);   // rows = k
    __syncthreads();
    #pragma unroll
    for (int j = 0; j < 4; j++) {
        int s = tid + j * 256;
        int kcl = s >> 8, n8l = (s >> 5) & 7, lane = s & 31;
        int gid = lane >> 2, tg = lane & 3;
        int nl = n8l * 8 + gid, kl = kcl * 16 + 2 * tg;
        uint2 h, l;
        split2(scale * t[kl][nl],     scale * t[kl + 1][nl], h.x, l.x);
        split2(scale * t[kl + 8][nl], scale * t[kl + 9][nl], h.y, l.y);
        size_t gb = (size_t)(k0 / 16 + kcl) * (N / 8) + (n0 / 8 + n8l);
        dst[gb * 64 + lane]      = h;
        dst[gb * 64 + 32 + lane] = l;
    }
}

// ---------------------------------------------------------------------------
// GEMM core: 256 threads, 128x128 tile, mega-stage BK=32, 2 buffers
// ---------------------------------------------------------------------------
#define MSTG 16384
#define SMEM_GEMM (4 * MSTG)   // 65536: A x2 + B x2

#define FRAG_COMPUTE(buf, kc)                                                 \
  do {                                                                        \
    uint4 ahq[4], alq[4];                                                     \
    uint2 bhp[4], blp[4];                                                     \
    _Pragma("unroll")                                                         \
    for (int mt = 0; mt < 4; mt++) {                                          \
      const char* p = dsm + (buf) * MSTG + (kc) * 8192                        \
                      + (wm * 4 + mt) * 1024 + lane * 16;                     \
      ahq[mt] = *(const uint4*)p;                                             \
      alq[mt] = *(const uint4*)(p + 512);                                     \
    }                                                                         \
    _Pragma("unroll")                                                         \
    for (int nt = 0; nt < 4; nt++) {                                          \
      const char* p = dsm + 2 * MSTG + (buf) * MSTG + (kc) * 8192             \
                      + (wn * 4 + nt) * 512 + lane * 8;                       \
      bhp[nt] = *(const uint2*)p;                                             \
      blp[nt] = *(const uint2*)(p + 256);                                     \
    }                                                                         \
    _Pragma("unroll")                                                         \
    for (int mt = 0; mt < 4; mt++)                                            \
      _Pragma("unroll")                                                       \
      for (int nt = 0; nt < 4; nt++) {                                        \
        mma16(acc[mt][nt], (const uint32_t*)&ahq[mt], (const uint32_t*)&bhp[nt]); \
        mma16(acc[mt][nt], (const uint32_t*)&ahq[mt], (const uint32_t*)&blp[nt]); \
        mma16(acc[mt][nt], (const uint32_t*)&alq[mt], (const uint32_t*)&bhp[nt]); \
      }                                                                       \
  } while (0)

#define ACC_INIT                                                              \
    float acc[4][4][4];                                                      \
    _Pragma("unroll")                                                         \
    for (int i = 0; i < 4; i++)                                               \
      _Pragma("unroll")                                                       \
      for (int j = 0; j < 4; j++)                                             \
        _Pragma("unroll")                                                     \
        for (int t = 0; t < 4; t++) acc[i][j][t] = 0.f;

#define WARP_IDS                                                              \
    const int tid = threadIdx.x;                                              \
    const int warp = tid >> 5, lane = tid & 31;                               \
    const int wm = warp & 1, wn = warp >> 1;                                  \
    const int gid = lane >> 2, tg = lane & 3;

#define PIPE_SMEM                                                             \
    extern __shared__ char dsm[];                                             \
    uint32_t smb;                                                             \
    asm("{ .reg .u64 t; cvta.to.shared.u64 t, %1; cvt.u32.u64 %0, t; }"       \
        : "=r"(smb) : "l"(dsm));

// One mega-stage = two k16 blocks of A (8KB each) + two of B.
#define ISSUE_M(s)                                                            \
    do {                                                                      \
        cpa(dA0 + (s) * MSTG, aPtr);                                          \
        cpa(dA0 + (s) * MSTG + 16, aPtr + 16);                                \
        cpa(dA0 + (s) * MSTG + 8192, aPtr + aStride);                         \
        cpa(dA0 + (s) * MSTG + 8192 + 16, aPtr + aStride + 16);               \
        cpa(dB0 + (s) * MSTG, bPtr);                                          \
        cpa(dB0 + (s) * MSTG + 16, bPtr + 16);                                \
        cpa(dB0 + (s) * MSTG + 8192, bPtr + bStride);                         \
        cpa(dB0 + (s) * MSTG + 8192 + 16, bPtr + bStride + 16);               \
        aPtr += 2 * aStride;                                                  \
        bPtr += 2 * bStride;                                                  \
    } while (0)

#define PIPE_MAINLOOP(NMEGA)                                                  \
    const uint32_t dA0 = smb + tid * 32;                                      \
    const uint32_t dB0 = smb + 2 * MSTG + tid * 32;                           \
    ISSUE_M(0); CP_COMMIT();                                                  \
    ISSUE_M(1); CP_COMMIT();                                                  \
    for (int i = 0; i < (NMEGA); i++) {                                       \
        CP_WAIT1();                                                           \
        __syncthreads();                                                      \
        int buf = i & 1;                                                      \
        FRAG_COMPUTE(buf, 0);                                                 \
        FRAG_COMPUTE(buf, 1);                                                 \
        __syncthreads();                                                      \
        if (i + 2 < (NMEGA)) { ISSUE_M(buf); CP_COMMIT(); }                   \
    }

// ---------------------------------------------------------------------------
// Merged projections: z in 0..4 selects {q, kt, vt, ke, ve}.
// z==0 also emits qF (A-frag); z==3 emits keF (B-frag) only.
// ---------------------------------------------------------------------------
__global__ void __launch_bounds__(256, 2) gemm_proj_all(
    const uint4* __restrict__ hsF, const uint4* __restrict__ exF,
    const uint2* __restrict__ wF,
    const float* __restrict__ bq, const float* __restrict__ bk,
    const float* __restrict__ bv,
    float* __restrict__ q, float* __restrict__ kt, float* __restrict__ vt,
    float* __restrict__ ve,
    uint4* __restrict__ qF, uint2* __restrict__ keF)
{
    const int z = blockIdx.z;
    const bool isExt = (z >= 3);
    if (isExt && blockIdx.y >= 16) return;

    PIPE_SMEM;
    const int ldM  = isExt ? BE : BS;
    const int wsel = isExt ? (z - 2) : z;
    const float* bias = (wsel == 0) ? bq : (wsel == 1) ? bk : bv;

    const int bm = blockIdx.y * 128;
    const int bn = blockIdx.x * 128;
    WARP_IDS;
    const char* aPtr = (const char*)(isExt ? exF : hsF)
                       + (size_t)(bm / 16) * 1024 + tid * 32;
    const char* bPtr = (const char*)(wF + (size_t)wsel * (Hh/16) * (Hh/8) * 64)
                       + (size_t)(bn / 8) * 512 + tid * 32;
    const size_t aStride = (size_t)(ldM / 16) * 1024;
    const size_t bStride = (size_t)(Hh / 8) * 512;

    ACC_INIT;
    PIPE_MAINLOOP(Hh / 32);

    #pragma unroll
    for (int mt = 0; mt < 4; mt++) {
        // Post-scaled outputs for this mt: o[nt][t]
        float o[4][4];
        #pragma unroll
        for (int nt = 0; nt < 4; nt++) {
            int col = bn + wn * 32 + nt * 8 + 2 * tg;
            float2 bi = *(const float2*)(bias + col);
            o[nt][0] = fmaf(acc[mt][nt][0], WINV, bi.x);
            o[nt][1] = fmaf(acc[mt][nt][1], WINV, bi.y);
            o[nt][2] = fmaf(acc[mt][nt][2], WINV, bi.x);
            o[nt][3] = fmaf(acc[mt][nt][3], WINV, bi.y);
        }

        if (z != 3) {   // fp32 output for q, kt, vt, ve
            float* C = (z == 0) ? q : (z == 1) ? kt : (z == 2) ? vt : ve;
            int r0 = bm + wm * 64 + mt * 16 + gid;
            #pragma unroll
            for (int nt = 0; nt < 4; nt++) {
                int col = bn + wn * 32 + nt * 8 + 2 * tg;
                *(float2*)(C + (size_t)r0 * Hh + col) =
                    make_float2(o[nt][0], o[nt][1]);
                *(float2*)(C + (size_t)(r0 + 8) * Hh + col) =
                    make_float2(o[nt][2], o[nt][3]);
            }
        }

        if (z == 0) {   // emit qF (A-frag for scores)
            int m16g = (bm >> 4) + wm * 4 + mt;
            #pragma unroll
            for (int p = 0; p < 2; p++) {
                int k16g = (bn >> 4) + wn * 2 + p;
                uint4 h, l;
                split2(o[2*p][0],   o[2*p][1],   h.x, l.x);
                split2(o[2*p][2],   o[2*p][3],   h.y, l.y);
                split2(o[2*p+1][0], o[2*p+1][1], h.z, l.z);
                split2(o[2*p+1][2], o[2*p+1][3], h.w, l.w);
                size_t gb = (size_t)k16g * (BS / 16) + m16g;
                qF[gb * 64 + lane]      = h;
                qF[gb * 64 + 32 + lane] = l;
            }
        }

        if (z == 3) {   // emit keF (B-frag for scores): n = e rows, k = Hh
            int e16 = (bm >> 4) + wm * 4 + mt;
            #pragma unroll
            for (int p = 0; p < 2; p++) {
                int k16g = (bn >> 4) + wn * 2 + p;
                uint2 hA, lA, hB, lB;
                split2(o[2*p][0],   o[2*p][1],   hA.x, lA.x);   // rows gid
                split2(o[2*p+1][0], o[2*p+1][1], hA.y, lA.y);
                split2(o[2*p][2],   o[2*p][3],   hB.x, lB.x);   // rows gid+8
                split2(o[2*p+1][2], o[2*p+1][3], hB.y, lB.y);
                size_t gbA = (size_t)k16g * (BE / 8) + 2 * e16;
                size_t gbB = gbA + 1;
                keF[gbA * 64 + lane]      = hA;
                keF[gbA * 64 + 32 + lane] = lA;
                keF[gbB * 64 + lane]      = hB;
                keF[gbB * 64 + 32 + lane] = lB;
            }
        }
    }
}

// ---------------------------------------------------------------------------
// Scores: SC[b, s, e] = Q . KE (K=1024).
// ---------------------------------------------------------------------------
__global__ void __launch_bounds__(256, 2) gemm_scores(
    const uint4* __restrict__ qF, const uint2* __restrict__ keF,
    float* __restrict__ SC)
{
    PIPE_SMEM;
    const int b = blockIdx.z;
    const int bm = b * Ss + blockIdx.y * 128;
    const int bn = b * Ee + blockIdx.x * 128;
    WARP_IDS;
    const char* aPtr = (const char*)qF + (size_t)(bm / 16) * 1024 + tid * 32;
    const char* bPtr = (const char*)keF + (size_t)(bn / 8) * 512 + tid * 32;
    const size_t aStride = (size_t)(BS / 16) * 1024;
    const size_t bStride = (size_t)(BE / 8) * 512;

    ACC_INIT;
    PIPE_MAINLOOP(Hh / 32);

    const int cb = blockIdx.x * 128;
    #pragma unroll
    for (int mt = 0; mt < 4; mt++) {
        int row = bm + wm * 64 + mt * 16 + gid;
        #pragma unroll
        for (int nt = 0; nt < 4; nt++) {
            int col = cb + wn * 32 + nt * 8 + 2 * tg;
            *(float2*)(SC + (size_t)row * 512 + col) =
                make_float2(acc[mt][nt][0], acc[mt][nt][1]);
            *(float2*)(SC + (size_t)(row + 8) * 512 + col) =
                make_float2(acc[mt][nt][2], acc[mt][nt][3]);
        }
    }
}

// ---------------------------------------------------------------------------
// Context: O = P @ VE + p0 * VT (K=512).
// ---------------------------------------------------------------------------
__global__ void __launch_bounds__(256, 2) gemm_ctx(
    const uint4* __restrict__ pF, const float* __restrict__ P0,
    const uint2* __restrict__ veF, const float* __restrict__ VT,
    float* __restrict__ O)
{
    PIPE_SMEM;
    const int b = blockIdx.z;
    const int bm = b * Ss + blockIdx.y * 128;
    const int bn = blockIdx.x * 128;
    WARP_IDS;
    const char* aPtr = (const char*)pF + (size_t)(bm / 16) * 1024 + tid * 32;
    const char* bPtr = (const char*)veF
        + ((size_t)(b * Ee / 16) * (Hh / 8) + bn / 8) * 512 + tid * 32;
    const size_t aStride = (size_t)(BS / 16) * 1024;
    const size_t bStride = (size_t)(Hh / 8) * 512;

    ACC_INIT;
    PIPE_MAINLOOP(Ee / 32);

    #pragma unroll
    for (int mt = 0; mt < 4; mt++) {
        int r0 = bm + wm * 64 + mt * 16 + gid;
        int r1 = r0 + 8;
        float p0 = P0[r0];
        float p1 = P0[r1];
        #pragma unroll
        for (int nt = 0; nt < 4; nt++) {
            int col = bn + wn * 32 + nt * 8 + 2 * tg;
            float2 v0 = *(const float2*)(VT + (size_t)r0 * Hh + col);
            float2 v1 = *(const float2*)(VT + (size_t)r1 * Hh + col);
            float2 o0 = make_float2(fmaf(p0, v0.x, acc[mt][nt][0]),
                                    fmaf(p0, v0.y, acc[mt][nt][1]));
            float2 o1 = make_float2(fmaf(p1, v1.x, acc[mt][nt][2]),
                                    fmaf(p1, v1.y, acc[mt][nt][3]));
            *(float2*)(O + (size_t)r0 * Hh + col) = o0;
            *(float2*)(O + (size_t)r1 * Hh + col) = o1;
        }
    }
}

// ---------------------------------------------------------------------------
// Self-dot + softmax (softmax scatters probs into A-frag layout)
// ---------------------------------------------------------------------------
__global__ void self_dot_kernel(const float* __restrict__ q,
                                const float* __restrict__ kt,
                                float* __restrict__ S0)
{
    int row  = blockIdx.x * 8 + (threadIdx.x >> 5);
    int lane = threadIdx.x & 31;
    const float4* q4 = (const float4*)(q  + (size_t)row * Hh);
    const float4* k4 = (const float4*)(kt + (size_t)row * Hh);
    float sum = 0.f;
    #pragma unroll
    for (int i = lane; i < Hh / 4; i += 32) {
        float4 a = q4[i], b = k4[i];
        sum += a.x * b.x + a.y * b.y + a.z * b.z + a.w * b.w;
    }
    #pragma unroll
    for (int o = 16; o; o >>= 1) sum += __shfl_xor_sync(0xffffffffu, sum, o);
    if (lane == 0) S0[row] = sum;
}

__global__ void softmax_kernel(const float* __restrict__ SC,
                               float* __restrict__ S0,
                               uint32_t* __restrict__ PF)
{
    const int row = blockIdx.x;
    const float* s = SC + (size_t)row * 512;
    const int tid = threadIdx.x;
    __shared__ float redm[4], reds[4];

    float4 v = ((const float4*)s)[tid];
    float s0 = S0[row];
    float lmax = fmaxf(fmaxf(v.x, v.y), fmaxf(v.z, v.w));
    if (tid == 0) lmax = fmaxf(lmax, s0);
    #pragma unroll
    for (int o = 16; o; o >>= 1)
        lmax = fmaxf(lmax, __shfl_xor_sync(0xffffffffu, lmax, o));
    if ((tid & 31) == 0) redm[tid >> 5] = lmax;
    __syncthreads();
    float m = fmaxf(fmaxf(redm[0], redm[1]), fmaxf(redm[2], redm[3]));

    v.x = expf(v.x - m); v.y = expf(v.y - m);
    v.z = expf(v.z - m); v.w = expf(v.w - m);
    float e0 = expf(s0 - m);
    float lsum = v.x + v.y + v.z + v.w + ((tid == 0) ? e0 : 0.f);
    #pragma unroll
    for (int o = 16; o; o >>= 1) lsum += __shfl_xor_sync(0xffffffffu, lsum, o);
    if ((tid & 31) == 0) reds[tid >> 5] = lsum;
    __syncthreads();
    float inv = 1.f / (reds[0] + reds[1] + reds[2] + reds[3]);

    uint32_t h[2], l[2];
    split2(v.x * inv, v.y * inv, h[0], l[0]);
    split2(v.z * inv, v.w * inv, h[1], l[1]);

    const int m16 = row >> 4, gid = row & 7, mhalf = (row >> 3) & 1;
    #pragma unroll
    for (int qq = 0; qq < 2; qq++) {
        int kp = 2 * tid + qq;
        int kc = kp >> 3, tg = kp & 3, khalf = (kp >> 2) & 1;
        int lane = gid * 4 + tg, comp = mhalf + 2 * khalf;
        size_t gb = (size_t)kc * (BS / 16) + m16;
        PF[(gb * 64 + lane) * 4 + comp]      = h[qq];
        PF[(gb * 64 + 32 + lane) * 4 + comp] = l[qq];
    }
    if (tid == 0) S0[row] = e0 * inv;
}

// ---------------------------------------------------------------------------
extern "C" void kernel_launch(void* const* d_in, const int* in_sizes, int n_in,
                              void* d_out, int out_size)
{
    const float* hs  = (const float*)d_in[0];
    const float* ext = (const float*)d_in[1];
    const float* Wq  = (const float*)d_in[2];
    const float* bq  = (const float*)d_in[3];
    const float* Wk  = (const float*)d_in[4];
    const float* bk  = (const float*)d_in[5];
    const float* Wv  = (const float*)d_in[6];
    const float* bv  = (const float*)d_in[7];
    float* out = (float*)d_out;

    float *q, *kt, *vt, *ve, *sc, *s0;
    uint4 *hsF, *exF, *qF, *pF;
    uint2 *wF, *keF, *veF;
    cudaGetSymbolAddress((void**)&q,   g_q);
    cudaGetSymbolAddress((void**)&kt,  g_kt);
    cudaGetSymbolAddress((void**)&vt,  g_vt);
    cudaGetSymbolAddress((void**)&ve,  g_ve);
    cudaGetSymbolAddress((void**)&sc,  g_sc);
    cudaGetSymbolAddress((void**)&s0,  g_s0);
    cudaGetSymbolAddress((void**)&hsF, g_hsF);
    cudaGetSymbolAddress((void**)&exF, g_exF);
    cudaGetSymbolAddress((void**)&qF,  g_qF);
    cudaGetSymbolAddress((void**)&pF,  g_pF);
    cudaGetSymbolAddress((void**)&wF,  g_wF);
    cudaGetSymbolAddress((void**)&keF, g_keF);
    cudaGetSymbolAddress((void**)&veF, g_veF);

    cudaFuncSetAttribute(gemm_proj_all,
        cudaFuncAttributeMaxDynamicSharedMemorySize, SMEM_GEMM);
    cudaFuncSetAttribute(gemm_scores,
        cudaFuncAttributeMaxDynamicSharedMemorySize, SMEM_GEMM);
    cudaFuncSetAttribute(gemm_ctx,
        cudaFuncAttributeMaxDynamicSharedMemorySize, SMEM_GEMM);

    const size_t WFOFF = (size_t)(Hh / 16) * (Hh / 8) * 64;   // uint2 per weight

    // Pre-convert inputs into fragment-major layouts
    conv_A<<<dim3(BS / 64, Hh / 64), 256>>>(hs,  hsF, BS, Hh);
    conv_A<<<dim3(BE / 64, Hh / 64), 256>>>(ext, exF, BE, Hh);
    conv_B<<<dim3(Hh / 64, Hh / 64), 256>>>(Wq, wF,             Hh, Hh, WSCALE);
    conv_B<<<dim3(Hh / 64, Hh / 64), 256>>>(Wk, wF + WFOFF,     Hh, Hh, WSCALE);
    conv_B<<<dim3(Hh / 64, Hh / 64), 256>>>(Wv, wF + 2 * WFOFF, Hh, Hh, WSCALE);

    // All 5 projections, one launch (qF/keF emitted in-epilogue)
    gemm_proj_all<<<dim3(8, BS / 128, 5), 256, SMEM_GEMM>>>(
        hsF, exF, wF, bq, bk, bv, q, kt, vt, ve, qF, keF);

    // ve -> B-frag for ctx
    conv_B<<<dim3(Hh / 64, BE / 64), 256>>>(ve, veF, BE, Hh, 1.0f);

    // Scores
    self_dot_kernel<<<BS / 8, 256>>>(q, kt, s0);
    gemm_scores<<<dim3(4, Ss / 128, Bb), 256, SMEM_GEMM>>>(qF, keF, sc);

    // Softmax (emits fragment-major probs)
    softmax_kernel<<<BS, 128>>>(sc, s0, (uint32_t*)pF);

    // Context
    gemm_ctx<<<dim3(8, Ss / 128, Bb), 256, SMEM_GEMM>>>(pF, s0, veF, vt, out);
}

// round 15
// speedup vs baseline: 1.1131x; 1.1131x over previous
#include <cuda_runtime.h>
#include <cuda_fp16.h>
#include <cstdint>
#include <math.h>

// Problem dims (fixed)
#define Bb 4
#define Ss 2048
#define Ee 512
#define Hh 1024
#define BS (Bb*Ss)
#define BE (Bb*Ee)

// fp32 scratch
__device__ float g_q [BS*Hh];
__device__ float g_kt[BS*Hh];
__device__ float g_vt[BS*Hh];
__device__ float g_ve[BE*Hh];
__device__ float g_sc[(size_t)BS*512];       // raw ext scores
__device__ float g_s0[BS];                   // self score / prob
// Fragment-major (hi,lo separated) scratch.
// A-frag: per (k16,m16) block: 32 x uint4 hi, 32 x uint4 lo (1024 B)
// B-frag: per (k16,n8)  block: 32 x uint2 hi, 32 x uint2 lo (512 B)
__device__ __align__(16) uint4 g_hsF[(size_t)BS*Hh/4];
__device__ __align__(16) uint4 g_exF[(size_t)BE*Hh/4];
__device__ __align__(16) uint4 g_qF [(size_t)BS*Hh/4];
__device__ __align__(16) uint4 g_pF [(size_t)BS*512/4];
__device__ __align__(16) uint2 g_wF [3*(size_t)Hh*Hh/2];
__device__ __align__(16) uint2 g_keF[(size_t)Hh*BE/2];
__device__ __align__(16) uint2 g_veF[(size_t)BE*Hh/2];

#define WSCALE 32.0f
#define WINV   (1.0f / 32.0f)

__device__ __forceinline__ void split2(float x, float y,
                                       uint32_t &h, uint32_t &l)
{
    asm("cvt.rn.f16x2.f32 %0, %1, %2;" : "=r"(h) : "f"(y), "f"(x));
    __half2 hv = *reinterpret_cast<__half2*>(&h);
    float2 b = __half22float2(hv);
    asm("cvt.rn.f16x2.f32 %0, %1, %2;" : "=r"(l) : "f"(y - b.y), "f"(x - b.x));
}

__device__ __forceinline__ void mma16(float* d, const uint32_t* a,
                                      const uint32_t* b)
{
    asm volatile(
        "mma.sync.aligned.m16n8k16.row.col.f32.f16.f16.f32 "
        "{%0,%1,%2,%3}, {%4,%5,%6,%7}, {%8,%9}, {%0,%1,%2,%3};"
        : "+f"(d[0]), "+f"(d[1]), "+f"(d[2]), "+f"(d[3])
        : "r"(a[0]), "r"(a[1]), "r"(a[2]), "r"(a[3]),
          "r"(b[0]), "r"(b[1]));
}

__device__ __forceinline__ void cpa(uint32_t d, const void* s)
{
    asm volatile("cp.async.cg.shared.global [%0], [%1], 16;"
                 :: "r"(d), "l"(s) : "memory");
}
#define CP_COMMIT() asm volatile("cp.async.commit_group;" ::: "memory")
#define CP_WAIT2()  asm volatile("cp.async.wait_group 2;" ::: "memory")

// ---------------------------------------------------------------------------
// Convert kernels (64x64 fp32 tile staged in smem, then fragment emit)
// ---------------------------------------------------------------------------
#define TILE_LOAD(src, ld, r0, c0)                                            \
    do {                                                                      \
        int r_ = tid >> 2, c4_ = (tid & 3) * 16;                              \
        _Pragma("unroll")                                                     \
        for (int i_ = 0; i_ < 4; i_++) {                                      \
            float4 v_ = *(const float4*)((src) + (size_t)((r0) + r_) * (ld)   \
                                         + (c0) + c4_ + i_ * 4);              \
            t[r_][c4_ + i_*4 + 0] = v_.x;                                     \
            t[r_][c4_ + i_*4 + 1] = v_.y;                                     \
            t[r_][c4_ + i_*4 + 2] = v_.z;                                     \
            t[r_][c4_ + i_*4 + 3] = v_.w;                                     \
        }                                                                     \
    } while (0)

// A-frag from src [M][K] f32. grid (M/64, K/64), 256 thr.
__global__ void conv_A(const float* __restrict__ src, uint4* __restrict__ dst,
                       int M, int K)
{
    __shared__ float t[64][65];
    const int tid = threadIdx.x;
    const int m0 = blockIdx.x * 64, k0 = blockIdx.y * 64;
    TILE_LOAD(src, K, m0, k0);
    __syncthreads();
    #pragma unroll
    for (int j = 0; j < 2; j++) {
        int s = tid + j * 256;
        int kcl = s >> 7, m16l = (s >> 5) & 3, lane = s & 31;
        int gid = lane >> 2, tg = lane & 3;
        int ml = m16l * 16 + gid, kl = kcl * 16 + 2 * tg;
        uint4 h, l;
        split2(t[ml][kl],       t[ml][kl + 1],       h.x, l.x);
        split2(t[ml + 8][kl],   t[ml + 8][kl + 1],   h.y, l.y);
        split2(t[ml][kl + 8],   t[ml][kl + 9],       h.z, l.z);
        split2(t[ml + 8][kl + 8], t[ml + 8][kl + 9], h.w, l.w);
        size_t gb = (size_t)(k0 / 16 + kcl) * (M / 16) + (m0 / 16 + m16l);
        dst[gb * 64 + lane]      = h;
        dst[gb * 64 + 32 + lane] = l;
    }
}

// B-frag from src [K][N] f32 (scaled). grid (N/64, K/64), 256 thr.
__global__ void conv_B(const float* __restrict__ src, uint2* __restrict__ dst,
                       int K, int N, float scale)
{
    __shared__ float t[64][65];
    const int tid = threadIdx.x;
    const int n0 = blockIdx.x * 64, k0 = blockIdx.y * 64;
    TILE_LOAD(src, N, k0, n0);   // rows = k
    __syncthreads();
    #pragma unroll
    for (int j = 0; j < 4; j++) {
        int s = tid + j * 256;
        int kcl = s >> 8, n8l = (s >> 5) & 7, lane = s & 31;
        int gid = lane >> 2, tg = lane & 3;
        int nl = n8l * 8 + gid, kl = kcl * 16 + 2 * tg;
        uint2 h, l;
        split2(scale * t[kl][nl],     scale * t[kl + 1][nl], h.x, l.x);
        split2(scale * t[kl + 8][nl], scale * t[kl + 9][nl], h.y, l.y);
        size_t gb = (size_t)(k0 / 16 + kcl) * (N / 8) + (n0 / 8 + n8l);
        dst[gb * 64 + lane]      = h;
        dst[gb * 64 + 32 + lane] = l;
    }
}

// ---------------------------------------------------------------------------
// GEMM core: 256 threads, 128x128 tile, BK=16, 4-stage cp.async pipe
// ---------------------------------------------------------------------------
#define STAGES 4
#define A_STG 8192
#define B_STG 8192
#define SMEM_GEMM ((A_STG + B_STG) * STAGES)   // 65536

#define FRAG_COMPUTE(j)                                                       \
  do {                                                                        \
    uint4 ahq[4], alq[4];                                                     \
    uint2 bhp[4], blp[4];                                                     \
    _Pragma("unroll")                                                         \
    for (int mt = 0; mt < 4; mt++) {                                          \
      const char* p = dsm + (j) * A_STG + (wm * 4 + mt) * 1024 + lane * 16;   \
      ahq[mt] = *(const uint4*)p;                                             \
      alq[mt] = *(const uint4*)(p + 512);                                     \
    }                                                                         \
    _Pragma("unroll")                                                         \
    for (int nt = 0; nt < 4; nt++) {                                          \
      const char* p = dsm + STAGES * A_STG + (j) * B_STG                      \
                      + (wn * 4 + nt) * 512 + lane * 8;                       \
      bhp[nt] = *(const uint2*)p;                                             \
      blp[nt] = *(const uint2*)(p + 256);                                     \
    }                                                                         \
    _Pragma("unroll")                                                         \
    for (int mt = 0; mt < 4; mt++)                                            \
      _Pragma("unroll")                                                       \
      for (int nt = 0; nt < 4; nt++) {                                        \
        mma16(acc[mt][nt], (const uint32_t*)&ahq[mt], (const uint32_t*)&bhp[nt]); \
        mma16(acc[mt][nt], (const uint32_t*)&ahq[mt], (const uint32_t*)&blp[nt]); \
        mma16(acc[mt][nt], (const uint32_t*)&alq[mt], (const uint32_t*)&bhp[nt]); \
      }                                                                       \
  } while (0)

#define ACC_INIT                                                              \
    float acc[4][4][4];                                                      \
    _Pragma("unroll")                                                         \
    for (int i = 0; i < 4; i++)                                               \
      _Pragma("unroll")                                                       \
      for (int j = 0; j < 4; j++)                                             \
        _Pragma("unroll")                                                     \
        for (int t = 0; t < 4; t++) acc[i][j][t] = 0.f;

#define WARP_IDS                                                              \
    const int tid = threadIdx.x;                                              \
    const int warp = tid >> 5, lane = tid & 31;                               \
    const int wm = warp & 1, wn = warp >> 1;                                  \
    const int gid = lane >> 2, tg = lane & 3;

#define PIPE_SMEM                                                             \
    extern __shared__ char dsm[];                                             \
    uint32_t smb;                                                             \
    asm("{ .reg .u64 t; cvta.to.shared.u64 t, %1; cvt.u32.u64 %0, t; }"       \
        : "=r"(smb) : "l"(dsm));

#define ISSUE_S(s)                                                            \
    do {                                                                      \
        cpa(dA0 + (s) * A_STG, aPtr);                                         \
        cpa(dA0 + (s) * A_STG + 16, aPtr + 16);                               \
        cpa(dB0 + (s) * B_STG, bPtr);                                         \
        cpa(dB0 + (s) * B_STG + 16, bPtr + 16);                               \
        aPtr += aStride;                                                      \
        bPtr += bStride;                                                      \
    } while (0)

// NST must be a multiple of 4.
#define PIPE_MAINLOOP(NST)                                                    \
    const uint32_t dA0 = smb + tid * 32;                                      \
    const uint32_t dB0 = smb + STAGES * A_STG + tid * 32;                     \
    ISSUE_S(0); CP_COMMIT();                                                  \
    ISSUE_S(1); CP_COMMIT();                                                  \
    ISSUE_S(2); CP_COMMIT();                                                  \
    for (int i = 0; i < (NST); i += 4) {                                      \
        _Pragma("unroll")                                                     \
        for (int j = 0; j < 4; j++) {                                         \
            CP_WAIT2();                                                       \
            __syncthreads();                                                  \
            if (i + j + 3 < (NST)) ISSUE_S((j + 3) & 3);                      \
            CP_COMMIT();                                                      \
            FRAG_COMPUTE(j);                                                  \
        }                                                                     \
    }

// ---------------------------------------------------------------------------
// Merged projections: z in 0..4 selects {q, kt, vt, ke, ve}.
// z==0 also emits qF (A-frag); z==3 emits keF (B-frag) only.
// ---------------------------------------------------------------------------
__global__ void __launch_bounds__(256, 2) gemm_proj_all(
    const uint4* __restrict__ hsF, const uint4* __restrict__ exF,
    const uint2* __restrict__ wF,
    const float* __restrict__ bq, const float* __restrict__ bk,
    const float* __restrict__ bv,
    float* __restrict__ q, float* __restrict__ kt, float* __restrict__ vt,
    float* __restrict__ ve,
    uint4* __restrict__ qF, uint2* __restrict__ keF)
{
    const int z = blockIdx.z;
    const bool isExt = (z >= 3);
    if (isExt && blockIdx.y >= 16) return;

    PIPE_SMEM;
    const int ldM  = isExt ? BE : BS;
    const int wsel = isExt ? (z - 2) : z;
    const float* bias = (wsel == 0) ? bq : (wsel == 1) ? bk : bv;

    const int bm = blockIdx.y * 128;
    const int bn = blockIdx.x * 128;
    WARP_IDS;
    const char* aPtr = (const char*)(isExt ? exF : hsF)
                       + (size_t)(bm / 16) * 1024 + tid * 32;
    const char* bPtr = (const char*)(wF + (size_t)wsel * (Hh/16) * (Hh/8) * 64)
                       + (size_t)(bn / 8) * 512 + tid * 32;
    const size_t aStride = (size_t)(ldM / 16) * 1024;
    const size_t bStride = (size_t)(Hh / 8) * 512;

    ACC_INIT;
    PIPE_MAINLOOP(Hh / 16);

    #pragma unroll
    for (int mt = 0; mt < 4; mt++) {
        float o[4][4];
        #pragma unroll
        for (int nt = 0; nt < 4; nt++) {
            int col = bn + wn * 32 + nt * 8 + 2 * tg;
            float2 bi = *(const float2*)(bias + col);
            o[nt][0] = fmaf(acc[mt][nt][0], WINV, bi.x);
            o[nt][1] = fmaf(acc[mt][nt][1], WINV, bi.y);
            o[nt][2] = fmaf(acc[mt][nt][2], WINV, bi.x);
            o[nt][3] = fmaf(acc[mt][nt][3], WINV, bi.y);
        }

        if (z != 3) {   // fp32 output for q, kt, vt, ve
            float* C = (z == 0) ? q : (z == 1) ? kt : (z == 2) ? vt : ve;
            int r0 = bm + wm * 64 + mt * 16 + gid;
            #pragma unroll
            for (int nt = 0; nt < 4; nt++) {
                int col = bn + wn * 32 + nt * 8 + 2 * tg;
                *(float2*)(C + (size_t)r0 * Hh + col) =
                    make_float2(o[nt][0], o[nt][1]);
                *(float2*)(C + (size_t)(r0 + 8) * Hh + col) =
                    make_float2(o[nt][2], o[nt][3]);
            }
        }

        if (z == 0) {   // emit qF (A-frag for scores)
            int m16g = (bm >> 4) + wm * 4 + mt;
            #pragma unroll
            for (int p = 0; p < 2; p++) {
                int k16g = (bn >> 4) + wn * 2 + p;
                uint4 h, l;
                split2(o[2*p][0],   o[2*p][1],   h.x, l.x);
                split2(o[2*p][2],   o[2*p][3],   h.y, l.y);
                split2(o[2*p+1][0], o[2*p+1][1], h.z, l.z);
                split2(o[2*p+1][2], o[2*p+1][3], h.w, l.w);
                size_t gb = (size_t)k16g * (BS / 16) + m16g;
                qF[gb * 64 + lane]      = h;
                qF[gb * 64 + 32 + lane] = l;
            }
        }

        if (z == 3) {   // emit keF (B-frag for scores): n = e rows, k = Hh
            int e16 = (bm >> 4) + wm * 4 + mt;
            #pragma unroll
            for (int p = 0; p < 2; p++) {
                int k16g = (bn >> 4) + wn * 2 + p;
                uint2 hA, lA, hB, lB;
                split2(o[2*p][0],   o[2*p][1],   hA.x, lA.x);   // rows gid
                split2(o[2*p+1][0], o[2*p+1][1], hA.y, lA.y);
                split2(o[2*p][2],   o[2*p][3],   hB.x, lB.x);   // rows gid+8
                split2(o[2*p+1][2], o[2*p+1][3], hB.y, lB.y);
                size_t gbA = (size_t)k16g * (BE / 8) + 2 * e16;
                size_t gbB = gbA + 1;
                keF[gbA * 64 + lane]      = hA;
                keF[gbA * 64 + 32 + lane] = lA;
                keF[gbB * 64 + lane]      = hB;
                keF[gbB * 64 + 32 + lane] = lB;
            }
        }
    }
}

// ---------------------------------------------------------------------------
// Scores: SC[b, s, e] = Q . KE (K=1024).
// ---------------------------------------------------------------------------
__global__ void __launch_bounds__(256, 2) gemm_scores(
    const uint4* __restrict__ qF, const uint2* __restrict__ keF,
    float* __restrict__ SC)
{
    PIPE_SMEM;
    const int b = blockIdx.z;
    const int bm = b * Ss + blockIdx.y * 128;
    const int bn = b * Ee + blockIdx.x * 128;
    WARP_IDS;
    const char* aPtr = (const char*)qF + (size_t)(bm / 16) * 1024 + tid * 32;
    const char* bPtr = (const char*)keF + (size_t)(bn / 8) * 512 + tid * 32;
    const size_t aStride = (size_t)(BS / 16) * 1024;
    const size_t bStride = (size_t)(BE / 8) * 512;

    ACC_INIT;
    PIPE_MAINLOOP(Hh / 16);

    const int cb = blockIdx.x * 128;
    #pragma unroll
    for (int mt = 0; mt < 4; mt++) {
        int row = bm + wm * 64 + mt * 16 + gid;
        #pragma unroll
        for (int nt = 0; nt < 4; nt++) {
            int col = cb + wn * 32 + nt * 8 + 2 * tg;
            *(float2*)(SC + (size_t)row * 512 + col) =
                make_float2(acc[mt][nt][0], acc[mt][nt][1]);
            *(float2*)(SC + (size_t)(row + 8) * 512 + col) =
                make_float2(acc[mt][nt][2], acc[mt][nt][3]);
        }
    }
}

// ---------------------------------------------------------------------------
// Context: O = P @ VE + p0 * VT (K=512).
// ---------------------------------------------------------------------------
__global__ void __launch_bounds__(256, 2) gemm_ctx(
    const uint4* __restrict__ pF, const float* __restrict__ P0,
    const uint2* __restrict__ veF, const float* __restrict__ VT,
    float* __restrict__ O)
{
    PIPE_SMEM;
    const int b = blockIdx.z;
    const int bm = b * Ss + blockIdx.y * 128;
    const int bn = blockIdx.x * 128;
    WARP_IDS;
    const char* aPtr = (const char*)pF + (size_t)(bm / 16) * 1024 + tid * 32;
    const char* bPtr = (const char*)veF
        + ((size_t)(b * Ee / 16) * (Hh / 8) + bn / 8) * 512 + tid * 32;
    const size_t aStride = (size_t)(BS / 16) * 1024;
    const size_t bStride = (size_t)(Hh / 8) * 512;

    ACC_INIT;
    PIPE_MAINLOOP(Ee / 16);

    #pragma unroll
    for (int mt = 0; mt < 4; mt++) {
        int r0 = bm + wm * 64 + mt * 16 + gid;
        int r1 = r0 + 8;
        float p0 = P0[r0];
        float p1 = P0[r1];
        #pragma unroll
        for (int nt = 0; nt < 4; nt++) {
            int col = bn + wn * 32 + nt * 8 + 2 * tg;
            float2 v0 = *(const float2*)(VT + (size_t)r0 * Hh + col);
            float2 v1 = *(const float2*)(VT + (size_t)r1 * Hh + col);
            float2 o0 = make_float2(fmaf(p0, v0.x, acc[mt][nt][0]),
                                    fmaf(p0, v0.y, acc[mt][nt][1]));
            float2 o1 = make_float2(fmaf(p1, v1.x, acc[mt][nt][2]),
                                    fmaf(p1, v1.y, acc[mt][nt][3]));
            *(float2*)(O + (size_t)r0 * Hh + col) = o0;
            *(float2*)(O + (size_t)r1 * Hh + col) = o1;
        }
    }
}

// ---------------------------------------------------------------------------
// Self-dot + softmax (softmax scatters probs into A-frag layout)
// ---------------------------------------------------------------------------
__global__ void self_dot_kernel(const float* __restrict__ q,
                                const float* __restrict__ kt,
                                float* __restrict__ S0)
{
    int row  = blockIdx.x * 8 + (threadIdx.x >> 5);
    int lane = threadIdx.x & 31;
    const float4* q4 = (const float4*)(q  + (size_t)row * Hh);
    const float4* k4 = (const float4*)(kt + (size_t)row * Hh);
    float sum = 0.f;
    #pragma unroll
    for (int i = lane; i < Hh / 4; i += 32) {
        float4 a = q4[i], b = k4[i];
        sum += a.x * b.x + a.y * b.y + a.z * b.z + a.w * b.w;
    }
    #pragma unroll
    for (int o = 16; o; o >>= 1) sum += __shfl_xor_sync(0xffffffffu, sum, o);
    if (lane == 0) S0[row] = sum;
}

__global__ void softmax_kernel(const float* __restrict__ SC,
                               float* __restrict__ S0,
                               uint32_t* __restrict__ PF)
{
    const int row = blockIdx.x;
    const float* s = SC + (size_t)row * 512;
    const int tid = threadIdx.x;
    __shared__ float redm[4], reds[4];

    float4 v = ((const float4*)s)[tid];
    float s0 = S0[row];
    float lmax = fmaxf(fmaxf(v.x, v.y), fmaxf(v.z, v.w));
    if (tid == 0) lmax = fmaxf(lmax, s0);
    #pragma unroll
    for (int o = 16; o; o >>= 1)
        lmax = fmaxf(lmax, __shfl_xor_sync(0xffffffffu, lmax, o));
    if ((tid & 31) == 0) redm[tid >> 5] = lmax;
    __syncthreads();
    float m = fmaxf(fmaxf(redm[0], redm[1]), fmaxf(redm[2], redm[3]));

    v.x = expf(v.x - m); v.y = expf(v.y - m);
    v.z = expf(v.z - m); v.w = expf(v.w - m);
    float e0 = expf(s0 - m);
    float lsum = v.x + v.y + v.z + v.w + ((tid == 0) ? e0 : 0.f);
    #pragma unroll
    for (int o = 16; o; o >>= 1) lsum += __shfl_xor_sync(0xffffffffu, lsum, o);
    if ((tid & 31) == 0) reds[tid >> 5] = lsum;
    __syncthreads();
    float inv = 1.f / (reds[0] + reds[1] + reds[2] + reds[3]);

    uint32_t h[2], l[2];
    split2(v.x * inv, v.y * inv, h[0], l[0]);
    split2(v.z * inv, v.w * inv, h[1], l[1]);

    const int m16 = row >> 4, gid = row & 7, mhalf = (row >> 3) & 1;
    #pragma unroll
    for (int qq = 0; qq < 2; qq++) {
        int kp = 2 * tid + qq;
        int kc = kp >> 3, tg = kp & 3, khalf = (kp >> 2) & 1;
        int lane = gid * 4 + tg, comp = mhalf + 2 * khalf;
        size_t gb = (size_t)kc * (BS / 16) + m16;
        PF[(gb * 64 + lane) * 4 + comp]      = h[qq];
        PF[(gb * 64 + 32 + lane) * 4 + comp] = l[qq];
    }
    if (tid == 0) S0[row] = e0 * inv;
}

// ---------------------------------------------------------------------------
extern "C" void kernel_launch(void* const* d_in, const int* in_sizes, int n_in,
                              void* d_out, int out_size)
{
    const float* hs  = (const float*)d_in[0];
    const float* ext = (const float*)d_in[1];
    const float* Wq  = (const float*)d_in[2];
    const float* bq  = (const float*)d_in[3];
    const float* Wk  = (const float*)d_in[4];
    const float* bk  = (const float*)d_in[5];
    const float* Wv  = (const float*)d_in[6];
    const float* bv  = (const float*)d_in[7];
    float* out = (float*)d_out;

    float *q, *kt, *vt, *ve, *sc, *s0;
    uint4 *hsF, *exF, *qF, *pF;
    uint2 *wF, *keF, *veF;
    cudaGetSymbolAddress((void**)&q,   g_q);
    cudaGetSymbolAddress((void**)&kt,  g_kt);
    cudaGetSymbolAddress((void**)&vt,  g_vt);
    cudaGetSymbolAddress((void**)&ve,  g_ve);
    cudaGetSymbolAddress((void**)&sc,  g_sc);
    cudaGetSymbolAddress((void**)&s0,  g_s0);
    cudaGetSymbolAddress((void**)&hsF, g_hsF);
    cudaGetSymbolAddress((void**)&exF, g_exF);
    cudaGetSymbolAddress((void**)&qF,  g_qF);
    cudaGetSymbolAddress((void**)&pF,  g_pF);
    cudaGetSymbolAddress((void**)&wF,  g_wF);
    cudaGetSymbolAddress((void**)&keF, g_keF);
    cudaGetSymbolAddress((void**)&veF, g_veF);

    cudaFuncSetAttribute(gemm_proj_all,
        cudaFuncAttributeMaxDynamicSharedMemorySize, SMEM_GEMM);
    cudaFuncSetAttribute(gemm_scores,
        cudaFuncAttributeMaxDynamicSharedMemorySize, SMEM_GEMM);
    cudaFuncSetAttribute(gemm_ctx,
        cudaFuncAttributeMaxDynamicSharedMemorySize, SMEM_GEMM);

    const size_t WFOFF = (size_t)(Hh / 16) * (Hh / 8) * 64;   // uint2 per weight

    // Pre-convert inputs into fragment-major layouts
    conv_A<<<dim3(BS / 64, Hh / 64), 256>>>(hs,  hsF, BS, Hh);
    conv_A<<<dim3(BE / 64, Hh / 64), 256>>>(ext, exF, BE, Hh);
    conv_B<<<dim3(Hh / 64, Hh / 64), 256>>>(Wq, wF,             Hh, Hh, WSCALE);
    conv_B<<<dim3(Hh / 64, Hh / 64), 256>>>(Wk, wF + WFOFF,     Hh, Hh, WSCALE);
    conv_B<<<dim3(Hh / 64, Hh / 64), 256>>>(Wv, wF + 2 * WFOFF, Hh, Hh, WSCALE);

    // All 5 projections, one launch (qF/keF emitted in-epilogue)
    gemm_proj_all<<<dim3(8, BS / 128, 5), 256, SMEM_GEMM>>>(
        hsF, exF, wF, bq, bk, bv, q, kt, vt, ve, qF, keF);

    // ve -> B-frag for ctx
    conv_B<<<dim3(Hh / 64, BE / 64), 256>>>(ve, veF, BE, Hh, 1.0f);

    // Scores
    self_dot_kernel<<<BS / 8, 256>>>(q, kt, s0);
    gemm_scores<<<dim3(4, Ss / 128, Bb), 256, SMEM_GEMM>>>(qF, keF, sc);

    // Softmax (emits fragment-major probs)
    softmax_kernel<<<BS, 128>>>(sc, s0, (uint32_t*)pF);

    // Context
    gemm_ctx<<<dim3(8, Ss / 128, Bb), 256, SMEM_GEMM>>>(pF, s0, veF, vt, out);
}

// round 16
// speedup vs baseline: 1.1299x; 1.0151x over previous
#include <cuda_runtime.h>
#include <cuda_fp16.h>
#include <cstdint>
#include <math.h>

// Problem dims (fixed)
#define Bb 4
#define Ss 2048
#define Ee 512
#define Hh 1024
#define BS (Bb*Ss)
#define BE (Bb*Ee)

// fp32 scratch
__device__ float g_q [BS*Hh];
__device__ float g_kt[BS*Hh];
__device__ float g_vt[BS*Hh];
__device__ float g_ve[BE*Hh];
__device__ float g_sc[(size_t)BS*512];       // raw ext scores
__device__ float g_s0[BS];                   // self score / prob
// Fragment-major scratch.
// A-frag: per (k16,m16) block: 32 x uint4 hi, 32 x uint4 lo (1024 B)
// B-frag: per (k16,n8)  block: 32 x uint4 (hi.x,hi.y,lo.x,lo.y) (512 B)
__device__ __align__(16) uint4 g_hsF[(size_t)BS*Hh/4];
__device__ __align__(16) uint4 g_exF[(size_t)BE*Hh/4];
__device__ __align__(16) uint4 g_qF [(size_t)BS*Hh/4];
__device__ __align__(16) uint4 g_pF [(size_t)BS*512/4];
__device__ __align__(16) uint4 g_wF [3*(size_t)(Hh/16)*(Hh/8)*32];
__device__ __align__(16) uint4 g_keF[(size_t)(Hh/16)*(BE/8)*32];
__device__ __align__(16) uint4 g_veF[(size_t)(BE/16)*(Hh/8)*32];

#define WSCALE 32.0f
#define WINV   (1.0f / 32.0f)

__device__ __forceinline__ void split2(float x, float y,
                                       uint32_t &h, uint32_t &l)
{
    asm("cvt.rn.f16x2.f32 %0, %1, %2;" : "=r"(h) : "f"(y), "f"(x));
    __half2 hv = *reinterpret_cast<__half2*>(&h);
    float2 b = __half22float2(hv);
    asm("cvt.rn.f16x2.f32 %0, %1, %2;" : "=r"(l) : "f"(y - b.y), "f"(x - b.x));
}

__device__ __forceinline__ void mma16(float* d, const uint32_t* a,
                                      const uint32_t* b)
{
    asm volatile(
        "mma.sync.aligned.m16n8k16.row.col.f32.f16.f16.f32 "
        "{%0,%1,%2,%3}, {%4,%5,%6,%7}, {%8,%9}, {%0,%1,%2,%3};"
        : "+f"(d[0]), "+f"(d[1]), "+f"(d[2]), "+f"(d[3])
        : "r"(a[0]), "r"(a[1]), "r"(a[2]), "r"(a[3]),
          "r"(b[0]), "r"(b[1]));
}

__device__ __forceinline__ void cpa(uint32_t d, const void* s)
{
    asm volatile("cp.async.cg.shared.global [%0], [%1], 16;"
                 :: "r"(d), "l"(s) : "memory");
}
#define CP_COMMIT() asm volatile("cp.async.commit_group;" ::: "memory")
#define CP_WAIT2()  asm volatile("cp.async.wait_group 2;" ::: "memory")

// ---------------------------------------------------------------------------
// Convert kernels
// ---------------------------------------------------------------------------
#define TILE_LOAD(src, ld, r0, c0)                                            \
    do {                                                                      \
        int r_ = tid >> 2, c4_ = (tid & 3) * 16;                              \
        _Pragma("unroll")                                                     \
        for (int i_ = 0; i_ < 4; i_++) {                                      \
            float4 v_ = *(const float4*)((src) + (size_t)((r0) + r_) * (ld)   \
                                         + (c0) + c4_ + i_ * 4);              \
            t[r_][c4_ + i_*4 + 0] = v_.x;                                     \
            t[r_][c4_ + i_*4 + 1] = v_.y;                                     \
            t[r_][c4_ + i_*4 + 2] = v_.z;                                     \
            t[r_][c4_ + i_*4 + 3] = v_.w;                                     \
        }                                                                     \
    } while (0)

// A-frag from src [M][K] f32. grid (M/64, K/64), 256 thr.
__global__ void conv_A(const float* __restrict__ src, uint4* __restrict__ dst,
                       int M, int K)
{
    __shared__ float t[64][65];
    const int tid = threadIdx.x;
    const int m0 = blockIdx.x * 64, k0 = blockIdx.y * 64;
    TILE_LOAD(src, K, m0, k0);
    __syncthreads();
    #pragma unroll
    for (int j = 0; j < 2; j++) {
        int s = tid + j * 256;
        int kcl = s >> 7, m16l = (s >> 5) & 3, lane = s & 31;
        int gid = lane >> 2, tg = lane & 3;
        int ml = m16l * 16 + gid, kl = kcl * 16 + 2 * tg;
        uint4 h, l;
        split2(t[ml][kl],       t[ml][kl + 1],       h.x, l.x);
        split2(t[ml + 8][kl],   t[ml + 8][kl + 1],   h.y, l.y);
        split2(t[ml][kl + 8],   t[ml][kl + 9],       h.z, l.z);
        split2(t[ml + 8][kl + 8], t[ml + 8][kl + 9], h.w, l.w);
        size_t gb = (size_t)(k0 / 16 + kcl) * (M / 16) + (m0 / 16 + m16l);
        dst[gb * 64 + lane]      = h;
        dst[gb * 64 + 32 + lane] = l;
    }
}

// B-frag (quad-interleaved) from src [K][N] f32 (scaled). grid (N/64, K/64).
__global__ void conv_B(const float* __restrict__ src, uint4* __restrict__ dst,
                       int K, int N, float scale)
{
    __shared__ float t[64][65];
    const int tid = threadIdx.x;
    const int n0 = blockIdx.x * 64, k0 = blockIdx.y * 64;
    TILE_LOAD(src, N, k0, n0);   // rows = k
    __syncthreads();
    #pragma unroll
    for (int j = 0; j < 4; j++) {
        int s = tid + j * 256;
        int kcl = s >> 8, n8l = (s >> 5) & 7, lane = s & 31;
        int gid = lane >> 2, tg = lane & 3;
        int nl = n8l * 8 + gid, kl = kcl * 16 + 2 * tg;
        uint2 h, l;
        split2(scale * t[kl][nl],     scale * t[kl + 1][nl], h.x, l.x);
        split2(scale * t[kl + 8][nl], scale * t[kl + 9][nl], h.y, l.y);
        size_t gb = (size_t)(k0 / 16 + kcl) * (N / 8) + (n0 / 8 + n8l);
        dst[gb * 32 + lane] = make_uint4(h.x, h.y, l.x, l.y);
    }
}

// ---------------------------------------------------------------------------
// GEMM core: 256 threads, 128x128 tile, BK=16, 4-stage cp.async pipe
// ---------------------------------------------------------------------------
#define STAGES 4
#define A_STG 8192
#define B_STG 8192
#define SMEM_GEMM ((A_STG + B_STG) * STAGES)   // 65536

#define FRAG_COMPUTE(j)                                                       \
  do {                                                                        \
    uint4 ahq[4], alq[4], bqv[4];                                             \
    _Pragma("unroll")                                                         \
    for (int mt = 0; mt < 4; mt++) {                                          \
      const char* p = dsm + (j) * A_STG + (wm * 4 + mt) * 1024 + lane * 16;   \
      ahq[mt] = *(const uint4*)p;                                             \
      alq[mt] = *(const uint4*)(p + 512);                                     \
    }                                                                         \
    _Pragma("unroll")                                                         \
    for (int nt = 0; nt < 4; nt++) {                                          \
      const char* p = dsm + STAGES * A_STG + (j) * B_STG                      \
                      + (wn * 4 + nt) * 512 + lane * 16;                      \
      bqv[nt] = *(const uint4*)p;                                             \
    }                                                                         \
    _Pragma("unroll")                                                         \
    for (int mt = 0; mt < 4; mt++)                                            \
      _Pragma("unroll")                                                       \
      for (int nt = 0; nt < 4; nt++) {                                        \
        mma16(acc[mt][nt], (const uint32_t*)&ahq[mt], (const uint32_t*)&bqv[nt].x); \
        mma16(acc[mt][nt], (const uint32_t*)&ahq[mt], (const uint32_t*)&bqv[nt].z); \
        mma16(acc[mt][nt], (const uint32_t*)&alq[mt], (const uint32_t*)&bqv[nt].x); \
      }                                                                       \
  } while (0)

#define ACC_INIT                                                              \
    float acc[4][4][4];                                                      \
    _Pragma("unroll")                                                         \
    for (int i = 0; i < 4; i++)                                               \
      _Pragma("unroll")                                                       \
      for (int j = 0; j < 4; j++)                                             \
        _Pragma("unroll")                                                     \
        for (int t = 0; t < 4; t++) acc[i][j][t] = 0.f;

#define WARP_IDS                                                              \
    const int tid = threadIdx.x;                                              \
    const int warp = tid >> 5, lane = tid & 31;                               \
    const int wm = warp & 1, wn = warp >> 1;                                  \
    const int gid = lane >> 2, tg = lane & 3;

#define PIPE_SMEM                                                             \
    extern __shared__ char dsm[];                                             \
    uint32_t smb;                                                             \
    asm("{ .reg .u64 t; cvta.to.shared.u64 t, %1; cvt.u32.u64 %0, t; }"       \
        : "=r"(smb) : "l"(dsm));

#define ISSUE_S(s)                                                            \
    do {                                                                      \
        cpa(dA0 + (s) * A_STG, aPtr);                                         \
        cpa(dA0 + (s) * A_STG + 16, aPtr + 16);                               \
        cpa(dB0 + (s) * B_STG, bPtr);                                         \
        cpa(dB0 + (s) * B_STG + 16, bPtr + 16);                               \
        aPtr += aStride;                                                      \
        bPtr += bStride;                                                      \
    } while (0)

// NST must be a multiple of 4.
#define PIPE_MAINLOOP(NST)                                                    \
    const uint32_t dA0 = smb + tid * 32;                                      \
    const uint32_t dB0 = smb + STAGES * A_STG + tid * 32;                     \
    ISSUE_S(0); CP_COMMIT();                                                  \
    ISSUE_S(1); CP_COMMIT();                                                  \
    ISSUE_S(2); CP_COMMIT();                                                  \
    for (int i = 0; i < (NST); i += 4) {                                      \
        _Pragma("unroll")                                                     \
        for (int j = 0; j < 4; j++) {                                         \
            CP_WAIT2();                                                       \
            __syncthreads();                                                  \
            if (i + j + 3 < (NST)) ISSUE_S((j + 3) & 3);                      \
            CP_COMMIT();                                                      \
            FRAG_COMPUTE(j);                                                  \
        }                                                                     \
    }

// ---------------------------------------------------------------------------
// Merged projections. Grid (8, 80, 3): z = weight {Wq,Wk,Wv};
// y<64 = token rows, y>=64 = ext rows (z==0 ext early-exits).
// z==0 token also emits qF; z==1 ext emits keF only; z==2 ext writes ve.
// ---------------------------------------------------------------------------
__global__ void __launch_bounds__(256, 2) gemm_proj_all(
    const uint4* __restrict__ hsF, const uint4* __restrict__ exF,
    const uint4* __restrict__ wF,
    const float* __restrict__ bq, const float* __restrict__ bk,
    const float* __restrict__ bv,
    float* __restrict__ q, float* __restrict__ kt, float* __restrict__ vt,
    float* __restrict__ ve,
    uint4* __restrict__ qF, uint4* __restrict__ keF)
{
    const int z = blockIdx.z;
    const bool isExt = (blockIdx.y >= 64);
    if (isExt && z == 0) return;
    const int my = isExt ? (blockIdx.y - 64) : blockIdx.y;

    PIPE_SMEM;
    const int ldM = isExt ? BE : BS;
    const float* bias = (z == 0) ? bq : (z == 1) ? bk : bv;

    const int bm = my * 128;
    const int bn = blockIdx.x * 128;
    WARP_IDS;
    const char* aPtr = (const char*)(isExt ? exF : hsF)
                       + (size_t)(bm / 16) * 1024 + tid * 32;
    const char* bPtr = (const char*)(wF + (size_t)z * (Hh/16) * (Hh/8) * 32)
                       + (size_t)(bn / 8) * 512 + tid * 32;
    const size_t aStride = (size_t)(ldM / 16) * 1024;
    const size_t bStride = (size_t)(Hh / 8) * 512;

    ACC_INIT;
    PIPE_MAINLOOP(Hh / 16);

    const bool keOnly = (isExt && z == 1);

    #pragma unroll
    for (int mt = 0; mt < 4; mt++) {
        float o[4][4];
        #pragma unroll
        for (int nt = 0; nt < 4; nt++) {
            int col = bn + wn * 32 + nt * 8 + 2 * tg;
            float2 bi = *(const float2*)(bias + col);
            o[nt][0] = fmaf(acc[mt][nt][0], WINV, bi.x);
            o[nt][1] = fmaf(acc[mt][nt][1], WINV, bi.y);
            o[nt][2] = fmaf(acc[mt][nt][2], WINV, bi.x);
            o[nt][3] = fmaf(acc[mt][nt][3], WINV, bi.y);
        }

        if (!keOnly) {   // fp32 output for q, kt, vt, ve
            float* C = (z == 0) ? q : (z == 1) ? kt : (isExt ? ve : vt);
            int r0 = bm + wm * 64 + mt * 16 + gid;
            #pragma unroll
            for (int nt = 0; nt < 4; nt++) {
                int col = bn + wn * 32 + nt * 8 + 2 * tg;
                *(float2*)(C + (size_t)r0 * Hh + col) =
                    make_float2(o[nt][0], o[nt][1]);
                *(float2*)(C + (size_t)(r0 + 8) * Hh + col) =
                    make_float2(o[nt][2], o[nt][3]);
            }
        }

        if (z == 0) {   // emit qF (A-frag for scores)
            int m16g = (bm >> 4) + wm * 4 + mt;
            #pragma unroll
            for (int p = 0; p < 2; p++) {
                int k16g = (bn >> 4) + wn * 2 + p;
                uint4 h, l;
                split2(o[2*p][0],   o[2*p][1],   h.x, l.x);
                split2(o[2*p][2],   o[2*p][3],   h.y, l.y);
                split2(o[2*p+1][0], o[2*p+1][1], h.z, l.z);
                split2(o[2*p+1][2], o[2*p+1][3], h.w, l.w);
                size_t gb = (size_t)k16g * (BS / 16) + m16g;
                qF[gb * 64 + lane]      = h;
                qF[gb * 64 + 32 + lane] = l;
            }
        }

        if (keOnly) {   // emit keF (quad B-frag for scores): n = e rows, k = Hh
            int e16 = (bm >> 4) + wm * 4 + mt;
            #pragma unroll
            for (int p = 0; p < 2; p++) {
                int k16g = (bn >> 4) + wn * 2 + p;
                uint2 hA, lA, hB, lB;
                split2(o[2*p][0],   o[2*p][1],   hA.x, lA.x);   // rows gid
                split2(o[2*p+1][0], o[2*p+1][1], hA.y, lA.y);
                split2(o[2*p][2],   o[2*p][3],   hB.x, lB.x);   // rows gid+8
                split2(o[2*p+1][2], o[2*p+1][3], hB.y, lB.y);
                size_t gbA = (size_t)k16g * (BE / 8) + 2 * e16;
                size_t gbB = gbA + 1;
                keF[gbA * 32 + lane] = make_uint4(hA.x, hA.y, lA.x, lA.y);
                keF[gbB * 32 + lane] = make_uint4(hB.x, hB.y, lB.x, lB.y);
            }
        }
    }
}

// ---------------------------------------------------------------------------
// Scores: SC[b, s, e] = Q . KE (K=1024).
// ---------------------------------------------------------------------------
__global__ void __launch_bounds__(256, 2) gemm_scores(
    const uint4* __restrict__ qF, const uint4* __restrict__ keF,
    float* __restrict__ SC)
{
    PIPE_SMEM;
    const int b = blockIdx.z;
    const int bm = b * Ss + blockIdx.y * 128;
    const int bn = b * Ee + blockIdx.x * 128;
    WARP_IDS;
    const char* aPtr = (const char*)qF + (size_t)(bm / 16) * 1024 + tid * 32;
    const char* bPtr = (const char*)keF + (size_t)(bn / 8) * 512 + tid * 32;
    const size_t aStride = (size_t)(BS / 16) * 1024;
    const size_t bStride = (size_t)(BE / 8) * 512;

    ACC_INIT;
    PIPE_MAINLOOP(Hh / 16);

    const int cb = blockIdx.x * 128;
    #pragma unroll
    for (int mt = 0; mt < 4; mt++) {
        int row = bm + wm * 64 + mt * 16 + gid;
        #pragma unroll
        for (int nt = 0; nt < 4; nt++) {
            int col = cb + wn * 32 + nt * 8 + 2 * tg;
            *(float2*)(SC + (size_t)row * 512 + col) =
                make_float2(acc[mt][nt][0], acc[mt][nt][1]);
            *(float2*)(SC + (size_t)(row + 8) * 512 + col) =
                make_float2(acc[mt][nt][2], acc[mt][nt][3]);
        }
    }
}

// ---------------------------------------------------------------------------
// Context: O = P @ VE + p0 * VT (K=512).
// ---------------------------------------------------------------------------
__global__ void __launch_bounds__(256, 2) gemm_ctx(
    const uint4* __restrict__ pF, const float* __restrict__ P0,
    const uint4* __restrict__ veF, const float* __restrict__ VT,
    float* __restrict__ O)
{
    PIPE_SMEM;
    const int b = blockIdx.z;
    const int bm = b * Ss + blockIdx.y * 128;
    const int bn = blockIdx.x * 128;
    WARP_IDS;
    const char* aPtr = (const char*)pF + (size_t)(bm / 16) * 1024 + tid * 32;
    const char* bPtr = (const char*)veF
        + ((size_t)(b * Ee / 16) * (Hh / 8) + bn / 8) * 512 + tid * 32;
    const size_t aStride = (size_t)(BS / 16) * 1024;
    const size_t bStride = (size_t)(Hh / 8) * 512;

    ACC_INIT;
    PIPE_MAINLOOP(Ee / 16);

    #pragma unroll
    for (int mt = 0; mt < 4; mt++) {
        int r0 = bm + wm * 64 + mt * 16 + gid;
        int r1 = r0 + 8;
        float p0 = P0[r0];
        float p1 = P0[r1];
        #pragma unroll
        for (int nt = 0; nt < 4; nt++) {
            int col = bn + wn * 32 + nt * 8 + 2 * tg;
            float2 v0 = *(const float2*)(VT + (size_t)r0 * Hh + col);
            float2 v1 = *(const float2*)(VT + (size_t)r1 * Hh + col);
            float2 o0 = make_float2(fmaf(p0, v0.x, acc[mt][nt][0]),
                                    fmaf(p0, v0.y, acc[mt][nt][1]));
            float2 o1 = make_float2(fmaf(p1, v1.x, acc[mt][nt][2]),
                                    fmaf(p1, v1.y, acc[mt][nt][3]));
            *(float2*)(O + (size_t)r0 * Hh + col) = o0;
            *(float2*)(O + (size_t)r1 * Hh + col) = o1;
        }
    }
}

// ---------------------------------------------------------------------------
// Self-dot + softmax (softmax scatters probs into A-frag layout)
// ---------------------------------------------------------------------------
__global__ void self_dot_kernel(const float* __restrict__ q,
                                const float* __restrict__ kt,
                                float* __restrict__ S0)
{
    int row  = blockIdx.x * 8 + (threadIdx.x >> 5);
    int lane = threadIdx.x & 31;
    const float4* q4 = (const float4*)(q  + (size_t)row * Hh);
    const float4* k4 = (const float4*)(kt + (size_t)row * Hh);
    float sum = 0.f;
    #pragma unroll
    for (int i = lane; i < Hh / 4; i += 32) {
        float4 a = q4[i], b = k4[i];
        sum += a.x * b.x + a.y * b.y + a.z * b.z + a.w * b.w;
    }
    #pragma unroll
    for (int o = 16; o; o >>= 1) sum += __shfl_xor_sync(0xffffffffu, sum, o);
    if (lane == 0) S0[row] = sum;
}

__global__ void softmax_kernel(const float* __restrict__ SC,
                               float* __restrict__ S0,
                               uint32_t* __restrict__ PF)
{
    const int row = blockIdx.x;
    const float* s = SC + (size_t)row * 512;
    const int tid = threadIdx.x;
    __shared__ float redm[4], reds[4];

    float4 v = ((const float4*)s)[tid];
    float s0 = S0[row];
    float lmax = fmaxf(fmaxf(v.x, v.y), fmaxf(v.z, v.w));
    if (tid == 0) lmax = fmaxf(lmax, s0);
    #pragma unroll
    for (int o = 16; o; o >>= 1)
        lmax = fmaxf(lmax, __shfl_xor_sync(0xffffffffu, lmax, o));
    if ((tid & 31) == 0) redm[tid >> 5] = lmax;
    __syncthreads();
    float m = fmaxf(fmaxf(redm[0], redm[1]), fmaxf(redm[2], redm[3]));

    v.x = expf(v.x - m); v.y = expf(v.y - m);
    v.z = expf(v.z - m); v.w = expf(v.w - m);
    float e0 = expf(s0 - m);
    float lsum = v.x + v.y + v.z + v.w + ((tid == 0) ? e0 : 0.f);
    #pragma unroll
    for (int o = 16; o; o >>= 1) lsum += __shfl_xor_sync(0xffffffffu, lsum, o);
    if ((tid & 31) == 0) reds[tid >> 5] = lsum;
    __syncthreads();
    float inv = 1.f / (reds[0] + reds[1] + reds[2] + reds[3]);

    uint32_t h[2], l[2];
    split2(v.x * inv, v.y * inv, h[0], l[0]);
    split2(v.z * inv, v.w * inv, h[1], l[1]);

    const int m16 = row >> 4, gid = row & 7, mhalf = (row >> 3) & 1;
    #pragma unroll
    for (int qq = 0; qq < 2; qq++) {
        int kp = 2 * tid + qq;
        int kc = kp >> 3, tg = kp & 3, khalf = (kp >> 2) & 1;
        int lane = gid * 4 + tg, comp = mhalf + 2 * khalf;
        size_t gb = (size_t)kc * (BS / 16) + m16;
        PF[(gb * 64 + lane) * 4 + comp]      = h[qq];
        PF[(gb * 64 + 32 + lane) * 4 + comp] = l[qq];
    }
    if (tid == 0) S0[row] = e0 * inv;
}

// ---------------------------------------------------------------------------
extern "C" void kernel_launch(void* const* d_in, const int* in_sizes, int n_in,
                              void* d_out, int out_size)
{
    const float* hs  = (const float*)d_in[0];
    const float* ext = (const float*)d_in[1];
    const float* Wq  = (const float*)d_in[2];
    const float* bq  = (const float*)d_in[3];
    const float* Wk  = (const float*)d_in[4];
    const float* bk  = (const float*)d_in[5];
    const float* Wv  = (const float*)d_in[6];
    const float* bv  = (const float*)d_in[7];
    float* out = (float*)d_out;

    float *q, *kt, *vt, *ve, *sc, *s0;
    uint4 *hsF, *exF, *qF, *pF, *wF, *keF, *veF;
    cudaGetSymbolAddress((void**)&q,   g_q);
    cudaGetSymbolAddress((void**)&kt,  g_kt);
    cudaGetSymbolAddress((void**)&vt,  g_vt);
    cudaGetSymbolAddress((void**)&ve,  g_ve);
    cudaGetSymbolAddress((void**)&sc,  g_sc);
    cudaGetSymbolAddress((void**)&s0,  g_s0);
    cudaGetSymbolAddress((void**)&hsF, g_hsF);
    cudaGetSymbolAddress((void**)&exF, g_exF);
    cudaGetSymbolAddress((void**)&qF,  g_qF);
    cudaGetSymbolAddress((void**)&pF,  g_pF);
    cudaGetSymbolAddress((void**)&wF,  g_wF);
    cudaGetSymbolAddress((void**)&keF, g_keF);
    cudaGetSymbolAddress((void**)&veF, g_veF);

    cudaFuncSetAttribute(gemm_proj_all,
        cudaFuncAttributeMaxDynamicSharedMemorySize, SMEM_GEMM);
    cudaFuncSetAttribute(gemm_scores,
        cudaFuncAttributeMaxDynamicSharedMemorySize, SMEM_GEMM);
    cudaFuncSetAttribute(gemm_ctx,
        cudaFuncAttributeMaxDynamicSharedMemorySize, SMEM_GEMM);

    const size_t WFOFF = (size_t)(Hh / 16) * (Hh / 8) * 32;   // uint4 per weight

    // Pre-convert inputs into fragment-major layouts
    conv_A<<<dim3(BS / 64, Hh / 64), 256>>>(hs,  hsF, BS, Hh);
    conv_A<<<dim3(BE / 64, Hh / 64), 256>>>(ext, exF, BE, Hh);
    conv_B<<<dim3(Hh / 64, Hh / 64), 256>>>(Wq, wF,             Hh, Hh, WSCALE);
    conv_B<<<dim3(Hh / 64, Hh / 64), 256>>>(Wk, wF + WFOFF,     Hh, Hh, WSCALE);
    conv_B<<<dim3(Hh / 64, Hh / 64), 256>>>(Wv, wF + 2 * WFOFF, Hh, Hh, WSCALE);

    // All 5 projections, one launch (qF/keF emitted in-epilogue)
    gemm_proj_all<<<dim3(8, 80, 3), 256, SMEM_GEMM>>>(
        hsF, exF, wF, bq, bk, bv, q, kt, vt, ve, qF, keF);

    // ve -> B-frag for ctx
    conv_B<<<dim3(Hh / 64, BE / 64), 256>>>(ve, veF, BE, Hh, 1.0f);

    // Scores
    self_dot_kernel<<<BS / 8, 256>>>(q, kt, s0);
    gemm_scores<<<dim3(4, Ss / 128, Bb), 256, SMEM_GEMM>>>(qF, keF, sc);

    // Softmax (emits fragment-major probs)
    softmax_kernel<<<BS, 128>>>(sc, s0, (uint32_t*)pF);

    // Context
    gemm_ctx<<<dim3(8, Ss / 128, Bb), 256, SMEM_GEMM>>>(pF, s0, veF, vt, out);
}

// round 17
// speedup vs baseline: 1.1425x; 1.0112x over previous
#include <cuda_runtime.h>
#include <cuda_fp16.h>
#include <cstdint>
#include <math.h>

// Problem dims (fixed)
#define Bb 4
#define Ss 2048
#define Ee 512
#define Hh 1024
#define BS (Bb*Ss)
#define BE (Bb*Ee)

// fp32 scratch
__device__ float g_q [BS*Hh];
__device__ float g_kt[BS*Hh];
__device__ float g_vt[BS*Hh];
__device__ float g_ve[BE*Hh];
__device__ float g_sc[(size_t)BS*512];       // raw ext scores
__device__ float g_s0[BS];                   // self score / prob
// Fragment-major scratch.
// A-frag: per (k16,m16) block: 32 x uint4 hi, 32 x uint4 lo (1024 B)
// B-frag: per (k16,n8)  block: 32 x uint4 (hi.x,hi.y,lo.x,lo.y) (512 B)
__device__ __align__(16) uint4 g_hsF[(size_t)BS*Hh/4];
__device__ __align__(16) uint4 g_exF[(size_t)BE*Hh/4];
__device__ __align__(16) uint4 g_qF [(size_t)BS*Hh/4];
__device__ __align__(16) uint4 g_pF [(size_t)BS*512/4];
__device__ __align__(16) uint4 g_wF [3*(size_t)(Hh/16)*(Hh/8)*32];
__device__ __align__(16) uint4 g_keF[(size_t)(Hh/16)*(BE/8)*32];
__device__ __align__(16) uint4 g_veF[(size_t)(BE/16)*(Hh/8)*32];

#define WSCALE 32.0f
#define WINV   (1.0f / 32.0f)
#define WFOFF4 ((size_t)(Hh/16)*(Hh/8)*32)   // uint4 per weight

__device__ __forceinline__ void split2(float x, float y,
                                       uint32_t &h, uint32_t &l)
{
    asm("cvt.rn.f16x2.f32 %0, %1, %2;" : "=r"(h) : "f"(y), "f"(x));
    __half2 hv = *reinterpret_cast<__half2*>(&h);
    float2 b = __half22float2(hv);
    asm("cvt.rn.f16x2.f32 %0, %1, %2;" : "=r"(l) : "f"(y - b.y), "f"(x - b.x));
}

__device__ __forceinline__ void mma16(float* d, const uint32_t* a,
                                      const uint32_t* b)
{
    asm volatile(
        "mma.sync.aligned.m16n8k16.row.col.f32.f16.f16.f32 "
        "{%0,%1,%2,%3}, {%4,%5,%6,%7}, {%8,%9}, {%0,%1,%2,%3};"
        : "+f"(d[0]), "+f"(d[1]), "+f"(d[2]), "+f"(d[3])
        : "r"(a[0]), "r"(a[1]), "r"(a[2]), "r"(a[3]),
          "r"(b[0]), "r"(b[1]));
}

__device__ __forceinline__ void cpa(uint32_t d, const void* s)
{
    asm volatile("cp.async.cg.shared.global [%0], [%1], 16;"
                 :: "r"(d), "l"(s) : "memory");
}
#define CP_COMMIT() asm volatile("cp.async.commit_group;" ::: "memory")
#define CP_WAIT2()  asm volatile("cp.async.wait_group 2;" ::: "memory")

// ---------------------------------------------------------------------------
// Conversion device functions (64x64 fp32 tile staged in smem)
// ---------------------------------------------------------------------------
__device__ __forceinline__ void tile_load(const float* src, int ld,
                                          int r0, int c0,
                                          float (*t)[65], int tid)
{
    int r_ = tid >> 2, c4_ = (tid & 3) * 16;
    #pragma unroll
    for (int i_ = 0; i_ < 4; i_++) {
        float4 v_ = *(const float4*)(src + (size_t)(r0 + r_) * ld
                                     + c0 + c4_ + i_ * 4);
        t[r_][c4_ + i_*4 + 0] = v_.x;
        t[r_][c4_ + i_*4 + 1] = v_.y;
        t[r_][c4_ + i_*4 + 2] = v_.z;
        t[r_][c4_ + i_*4 + 3] = v_.w;
    }
}

// A-frag from src [M][K] f32, tile (bx,by).
__device__ __forceinline__ void devconv_A(const float* src, uint4* dst,
                                          int M, int K, int bx, int by,
                                          float (*t)[65], int tid)
{
    const int m0 = bx * 64, k0 = by * 64;
    tile_load(src, K, m0, k0, t, tid);
    __syncthreads();
    #pragma unroll
    for (int j = 0; j < 2; j++) {
        int s = tid + j * 256;
        int kcl = s >> 7, m16l = (s >> 5) & 3, lane = s & 31;
        int gid = lane >> 2, tg = lane & 3;
        int ml = m16l * 16 + gid, kl = kcl * 16 + 2 * tg;
        uint4 h, l;
        split2(t[ml][kl],       t[ml][kl + 1],       h.x, l.x);
        split2(t[ml + 8][kl],   t[ml + 8][kl + 1],   h.y, l.y);
        split2(t[ml][kl + 8],   t[ml][kl + 9],       h.z, l.z);
        split2(t[ml + 8][kl + 8], t[ml + 8][kl + 9], h.w, l.w);
        size_t gb = (size_t)(k0 / 16 + kcl) * (M / 16) + (m0 / 16 + m16l);
        dst[gb * 64 + lane]      = h;
        dst[gb * 64 + 32 + lane] = l;
    }
}

// B-frag (quad) from src [K][N] f32 (scaled), tile (bx=n-tile, by=k-tile).
__device__ __forceinline__ void devconv_B(const float* src, uint4* dst,
                                          int K, int N, float scale,
                                          int bx, int by,
                                          float (*t)[65], int tid)
{
    const int n0 = bx * 64, k0 = by * 64;
    tile_load(src, N, k0, n0, t, tid);   // rows = k
    __syncthreads();
    #pragma unroll
    for (int j = 0; j < 4; j++) {
        int s = tid + j * 256;
        int kcl = s >> 8, n8l = (s >> 5) & 7, lane = s & 31;
        int gid = lane >> 2, tg = lane & 3;
        int nl = n8l * 8 + gid, kl = kcl * 16 + 2 * tg;
        uint2 h, l;
        split2(scale * t[kl][nl],     scale * t[kl + 1][nl], h.x, l.x);
        split2(scale * t[kl + 8][nl], scale * t[kl + 9][nl], h.y, l.y);
        size_t gb = (size_t)(k0 / 16 + kcl) * (N / 8) + (n0 / 8 + n8l);
        dst[gb * 32 + lane] = make_uint4(h.x, h.y, l.x, l.y);
    }
}

// Merged input conversions: flat grid 3328 blocks.
// [0,2048) hs A-conv; [2048,2560) ext A-conv; [2560,3328) Wq/Wk/Wv B-conv.
__global__ void conv_all(const float* __restrict__ hs,
                         const float* __restrict__ ext,
                         const float* __restrict__ Wq,
                         const float* __restrict__ Wk,
                         const float* __restrict__ Wv,
                         uint4* __restrict__ hsF, uint4* __restrict__ exF,
                         uint4* __restrict__ wF)
{
    __shared__ float t[64][65];
    const int tid = threadIdx.x;
    const int id = blockIdx.x;
    if (id < 2048) {
        devconv_A(hs, hsF, BS, Hh, id & 127, id >> 7, t, tid);
    } else if (id < 2560) {
        int r = id - 2048;
        devconv_A(ext, exF, BE, Hh, r & 31, r >> 5, t, tid);
    } else {
        int r = id - 2560;
        int w = r >> 8;
        int b = r & 255;
        const float* src = (w == 0) ? Wq : (w == 1) ? Wk : Wv;
        devconv_B(src, wF + (size_t)w * WFOFF4, Hh, Hh, WSCALE,
                  b & 15, b >> 4, t, tid);
    }
}

// Standalone B-conv for ve (depends on projections).
__global__ void conv_B(const float* __restrict__ src, uint4* __restrict__ dst,
                       int K, int N, float scale)
{
    __shared__ float t[64][65];
    devconv_B(src, dst, K, N, scale, blockIdx.x, blockIdx.y, t, threadIdx.x);
}

// ---------------------------------------------------------------------------
// GEMM core 128x128: 256 threads, BK=16, 4-stage cp.async pipe
// ---------------------------------------------------------------------------
#define STAGES 4
#define A_STG 8192
#define B_STG 8192
#define SMEM_GEMM ((A_STG + B_STG) * STAGES)   // 65536

#define FRAG_COMPUTE(j)                                                       \
  do {                                                                        \
    uint4 ahq[4], alq[4], bqv[4];                                             \
    _Pragma("unroll")                                                         \
    for (int mt = 0; mt < 4; mt++) {                                          \
      const char* p = dsm + (j) * A_STG + (wm * 4 + mt) * 1024 + lane * 16;   \
      ahq[mt] = *(const uint4*)p;                                             \
      alq[mt] = *(const uint4*)(p + 512);                                     \
    }                                                                         \
    _Pragma("unroll")                                                         \
    for (int nt = 0; nt < 4; nt++) {                                          \
      const char* p = dsm + STAGES * A_STG + (j) * B_STG                      \
                      + (wn * 4 + nt) * 512 + lane * 16;                      \
      bqv[nt] = *(const uint4*)p;                                             \
    }                                                                         \
    _Pragma("unroll")                                                         \
    for (int mt = 0; mt < 4; mt++)                                            \
      _Pragma("unroll")                                                       \
      for (int nt = 0; nt < 4; nt++) {                                        \
        mma16(acc[mt][nt], (const uint32_t*)&ahq[mt], (const uint32_t*)&bqv[nt].x); \
        mma16(acc[mt][nt], (const uint32_t*)&ahq[mt], (const uint32_t*)&bqv[nt].z); \
        mma16(acc[mt][nt], (const uint32_t*)&alq[mt], (const uint32_t*)&bqv[nt].x); \
      }                                                                       \
  } while (0)

#define ACC_INIT                                                              \
    float acc[4][4][4];                                                      \
    _Pragma("unroll")                                                         \
    for (int i = 0; i < 4; i++)                                               \
      _Pragma("unroll")                                                       \
      for (int j = 0; j < 4; j++)                                             \
        _Pragma("unroll")                                                     \
        for (int t = 0; t < 4; t++) acc[i][j][t] = 0.f;

#define WARP_IDS                                                              \
    const int tid = threadIdx.x;                                              \
    const int warp = tid >> 5, lane = tid & 31;                               \
    const int wm = warp & 1, wn = warp >> 1;                                  \
    const int gid = lane >> 2, tg = lane & 3;

#define PIPE_SMEM                                                             \
    extern __shared__ char dsm[];                                             \
    uint32_t smb;                                                             \
    asm("{ .reg .u64 t; cvta.to.shared.u64 t, %1; cvt.u32.u64 %0, t; }"       \
        : "=r"(smb) : "l"(dsm));

#define ISSUE_S(s)                                                            \
    do {                                                                      \
        cpa(dA0 + (s) * A_STG, aPtr);                                         \
        cpa(dA0 + (s) * A_STG + 16, aPtr + 16);                               \
        cpa(dB0 + (s) * B_STG, bPtr);                                         \
        cpa(dB0 + (s) * B_STG + 16, bPtr + 16);                               \
        aPtr += aStride;                                                      \
        bPtr += bStride;                                                      \
    } while (0)

// NST must be a multiple of 4.
#define PIPE_MAINLOOP(NST)                                                    \
    const uint32_t dA0 = smb + tid * 32;                                      \
    const uint32_t dB0 = smb + STAGES * A_STG + tid * 32;                     \
    ISSUE_S(0); CP_COMMIT();                                                  \
    ISSUE_S(1); CP_COMMIT();                                                  \
    ISSUE_S(2); CP_COMMIT();                                                  \
    for (int i = 0; i < (NST); i += 4) {                                      \
        _Pragma("unroll")                                                     \
        for (int j = 0; j < 4; j++) {                                         \
            CP_WAIT2();                                                       \
            __syncthreads();                                                  \
            if (i + j + 3 < (NST)) ISSUE_S((j + 3) & 3);                      \
            CP_COMMIT();                                                      \
            FRAG_COMPUTE(j);                                                  \
        }                                                                     \
    }

// ---------------------------------------------------------------------------
// Merged projections. Grid (8, 80, 3): z = weight {Wq,Wk,Wv};
// y<64 token rows, y>=64 ext rows. z==0 token emits qF; z==1 ext emits keF.
// ---------------------------------------------------------------------------
__global__ void __launch_bounds__(256, 2) gemm_proj_all(
    const uint4* __restrict__ hsF, const uint4* __restrict__ exF,
    const uint4* __restrict__ wF,
    const float* __restrict__ bq, const float* __restrict__ bk,
    const float* __restrict__ bv,
    float* __restrict__ q, float* __restrict__ kt, float* __restrict__ vt,
    float* __restrict__ ve,
    uint4* __restrict__ qF, uint4* __restrict__ keF)
{
    const int z = blockIdx.z;
    const bool isExt = (blockIdx.y >= 64);
    if (isExt && z == 0) return;
    const int my = isExt ? (blockIdx.y - 64) : blockIdx.y;

    PIPE_SMEM;
    const int ldM = isExt ? BE : BS;
    const float* bias = (z == 0) ? bq : (z == 1) ? bk : bv;

    const int bm = my * 128;
    const int bn = blockIdx.x * 128;
    WARP_IDS;
    const char* aPtr = (const char*)(isExt ? exF : hsF)
                       + (size_t)(bm / 16) * 1024 + tid * 32;
    const char* bPtr = (const char*)(wF + (size_t)z * WFOFF4)
                       + (size_t)(bn / 8) * 512 + tid * 32;
    const size_t aStride = (size_t)(ldM / 16) * 1024;
    const size_t bStride = (size_t)(Hh / 8) * 512;

    ACC_INIT;
    PIPE_MAINLOOP(Hh / 16);

    const bool keOnly = (isExt && z == 1);

    #pragma unroll
    for (int mt = 0; mt < 4; mt++) {
        float o[4][4];
        #pragma unroll
        for (int nt = 0; nt < 4; nt++) {
            int col = bn + wn * 32 + nt * 8 + 2 * tg;
            float2 bi = *(const float2*)(bias + col);
            o[nt][0] = fmaf(acc[mt][nt][0], WINV, bi.x);
            o[nt][1] = fmaf(acc[mt][nt][1], WINV, bi.y);
            o[nt][2] = fmaf(acc[mt][nt][2], WINV, bi.x);
            o[nt][3] = fmaf(acc[mt][nt][3], WINV, bi.y);
        }

        if (!keOnly) {
            float* C = (z == 0) ? q : (z == 1) ? kt : (isExt ? ve : vt);
            int r0 = bm + wm * 64 + mt * 16 + gid;
            #pragma unroll
            for (int nt = 0; nt < 4; nt++) {
                int col = bn + wn * 32 + nt * 8 + 2 * tg;
                *(float2*)(C + (size_t)r0 * Hh + col) =
                    make_float2(o[nt][0], o[nt][1]);
                *(float2*)(C + (size_t)(r0 + 8) * Hh + col) =
                    make_float2(o[nt][2], o[nt][3]);
            }
        }

        if (z == 0) {   // qF (A-frag for scores)
            int m16g = (bm >> 4) + wm * 4 + mt;
            #pragma unroll
            for (int p = 0; p < 2; p++) {
                int k16g = (bn >> 4) + wn * 2 + p;
                uint4 h, l;
                split2(o[2*p][0],   o[2*p][1],   h.x, l.x);
                split2(o[2*p][2],   o[2*p][3],   h.y, l.y);
                split2(o[2*p+1][0], o[2*p+1][1], h.z, l.z);
                split2(o[2*p+1][2], o[2*p+1][3], h.w, l.w);
                size_t gb = (size_t)k16g * (BS / 16) + m16g;
                qF[gb * 64 + lane]      = h;
                qF[gb * 64 + 32 + lane] = l;
            }
        }

        if (keOnly) {   // keF (quad B-frag for scores)
            int e16 = (bm >> 4) + wm * 4 + mt;
            #pragma unroll
            for (int p = 0; p < 2; p++) {
                int k16g = (bn >> 4) + wn * 2 + p;
                uint2 hA, lA, hB, lB;
                split2(o[2*p][0],   o[2*p][1],   hA.x, lA.x);
                split2(o[2*p+1][0], o[2*p+1][1], hA.y, lA.y);
                split2(o[2*p][2],   o[2*p][3],   hB.x, lB.x);
                split2(o[2*p+1][2], o[2*p+1][3], hB.y, lB.y);
                size_t gbA = (size_t)k16g * (BE / 8) + 2 * e16;
                size_t gbB = gbA + 1;
                keF[gbA * 32 + lane] = make_uint4(hA.x, hA.y, lA.x, lA.y);
                keF[gbB * 32 + lane] = make_uint4(hB.x, hB.y, lB.x, lB.y);
            }
        }
    }
}

// ---------------------------------------------------------------------------
// Scores: 64(M) x 128(N) tile, grid (4, 32, 4) = 512 CTAs.
// ---------------------------------------------------------------------------
#define A_STG_S 4096
#define B_STG_S 8192
#define SMEM_S ((A_STG_S + B_STG_S) * STAGES)   // 49152

__global__ void __launch_bounds__(256, 2) gemm_scores(
    const uint4* __restrict__ qF, const uint4* __restrict__ keF,
    float* __restrict__ SC)
{
    PIPE_SMEM;
    const int b = blockIdx.z;
    const int bm = b * Ss + blockIdx.y * 64;
    const int bn = b * Ee + blockIdx.x * 128;
    const int tid = threadIdx.x;
    const int warp = tid >> 5, lane = tid & 31;
    const int wm = warp & 1, wn = warp >> 1;
    const int gid = lane >> 2, tg = lane & 3;

    const char* aPtr = (const char*)qF + (size_t)(bm / 16) * 1024 + tid * 16;
    const char* bPtr = (const char*)keF + (size_t)(bn / 8) * 512 + tid * 32;
    const size_t aStride = (size_t)(BS / 16) * 1024;
    const size_t bStride = (size_t)(BE / 8) * 512;

    float acc[2][4][4];
    #pragma unroll
    for (int i = 0; i < 2; i++)
        #pragma unroll
        for (int j = 0; j < 4; j++)
            #pragma unroll
            for (int t = 0; t < 4; t++) acc[i][j][t] = 0.f;

    const uint32_t dA0 = smb + tid * 16;
    const uint32_t dB0 = smb + STAGES * A_STG_S + tid * 32;

#define ISSUE_SC(s)                                                           \
    do {                                                                      \
        cpa(dA0 + (s) * A_STG_S, aPtr);                                       \
        cpa(dB0 + (s) * B_STG_S, bPtr);                                       \
        cpa(dB0 + (s) * B_STG_S + 16, bPtr + 16);                             \
        aPtr += aStride;                                                      \
        bPtr += bStride;                                                      \
    } while (0)
#define FRAG_SC(j)                                                            \
  do {                                                                        \
    uint4 ahq[2], alq[2], bqv[4];                                             \
    _Pragma("unroll")                                                         \
    for (int mt = 0; mt < 2; mt++) {                                          \
      const char* p = dsm + (j) * A_STG_S + (wm * 2 + mt) * 1024 + lane * 16; \
      ahq[mt] = *(const uint4*)p;                                             \
      alq[mt] = *(const uint4*)(p + 512);                                     \
    }                                                                         \
    _Pragma("unroll")                                                         \
    for (int nt = 0; nt < 4; nt++) {                                          \
      const char* p = dsm + STAGES * A_STG_S + (j) * B_STG_S                  \
                      + (wn * 4 + nt) * 512 + lane * 16;                      \
      bqv[nt] = *(const uint4*)p;                                             \
    }                                                                         \
    _Pragma("unroll")                                                         \
    for (int mt = 0; mt < 2; mt++)                                            \
      _Pragma("unroll")                                                       \
      for (int nt = 0; nt < 4; nt++) {                                        \
        mma16(acc[mt][nt], (const uint32_t*)&ahq[mt], (const uint32_t*)&bqv[nt].x); \
        mma16(acc[mt][nt], (const uint32_t*)&ahq[mt], (const uint32_t*)&bqv[nt].z); \
        mma16(acc[mt][nt], (const uint32_t*)&alq[mt], (const uint32_t*)&bqv[nt].x); \
      }                                                                       \
  } while (0)

    ISSUE_SC(0); CP_COMMIT();
    ISSUE_SC(1); CP_COMMIT();
    ISSUE_SC(2); CP_COMMIT();
    for (int i = 0; i < Hh / 16; i += 4) {
        #pragma unroll
        for (int j = 0; j < 4; j++) {
            CP_WAIT2();
            __syncthreads();
            if (i + j + 3 < Hh / 16) ISSUE_SC((j + 3) & 3);
            CP_COMMIT();
            FRAG_SC(j);
        }
    }

    const int cb = blockIdx.x * 128;
    #pragma unroll
    for (int mt = 0; mt < 2; mt++) {
        int row = bm + wm * 32 + mt * 16 + gid;
        #pragma unroll
        for (int nt = 0; nt < 4; nt++) {
            int col = cb + wn * 32 + nt * 8 + 2 * tg;
            *(float2*)(SC + (size_t)row * 512 + col) =
                make_float2(acc[mt][nt][0], acc[mt][nt][1]);
            *(float2*)(SC + (size_t)(row + 8) * 512 + col) =
                make_float2(acc[mt][nt][2], acc[mt][nt][3]);
        }
    }
}

// ---------------------------------------------------------------------------
// Context: O = P @ VE + p0 * VT (K=512).
// ---------------------------------------------------------------------------
__global__ void __launch_bounds__(256, 2) gemm_ctx(
    const uint4* __restrict__ pF, const float* __restrict__ P0,
    const uint4* __restrict__ veF, const float* __restrict__ VT,
    float* __restrict__ O)
{
    PIPE_SMEM;
    const int b = blockIdx.z;
    const int bm = b * Ss + blockIdx.y * 128;
    const int bn = blockIdx.x * 128;
    WARP_IDS;
    const char* aPtr = (const char*)pF + (size_t)(bm / 16) * 1024 + tid * 32;
    const char* bPtr = (const char*)veF
        + ((size_t)(b * Ee / 16) * (Hh / 8) + bn / 8) * 512 + tid * 32;
    const size_t aStride = (size_t)(BS / 16) * 1024;
    const size_t bStride = (size_t)(Hh / 8) * 512;

    ACC_INIT;
    PIPE_MAINLOOP(Ee / 16);

    #pragma unroll
    for (int mt = 0; mt < 4; mt++) {
        int r0 = bm + wm * 64 + mt * 16 + gid;
        int r1 = r0 + 8;
        float p0 = P0[r0];
        float p1 = P0[r1];
        #pragma unroll
        for (int nt = 0; nt < 4; nt++) {
            int col = bn + wn * 32 + nt * 8 + 2 * tg;
            float2 v0 = *(const float2*)(VT + (size_t)r0 * Hh + col);
            float2 v1 = *(const float2*)(VT + (size_t)r1 * Hh + col);
            float2 o0 = make_float2(fmaf(p0, v0.x, acc[mt][nt][0]),
                                    fmaf(p0, v0.y, acc[mt][nt][1]));
            float2 o1 = make_float2(fmaf(p1, v1.x, acc[mt][nt][2]),
                                    fmaf(p1, v1.y, acc[mt][nt][3]));
            *(float2*)(O + (size_t)r0 * Hh + col) = o0;
            *(float2*)(O + (size_t)r1 * Hh + col) = o1;
        }
    }
}

// ---------------------------------------------------------------------------
// Self-dot + softmax (softmax scatters probs into A-frag layout)
// ---------------------------------------------------------------------------
__global__ void self_dot_kernel(const float* __restrict__ q,
                                const float* __restrict__ kt,
                                float* __restrict__ S0)
{
    int row  = blockIdx.x * 8 + (threadIdx.x >> 5);
    int lane = threadIdx.x & 31;
    const float4* q4 = (const float4*)(q  + (size_t)row * Hh);
    const float4* k4 = (const float4*)(kt + (size_t)row * Hh);
    float sum = 0.f;
    #pragma unroll
    for (int i = lane; i < Hh / 4; i += 32) {
        float4 a = q4[i], b = k4[i];
        sum += a.x * b.x + a.y * b.y + a.z * b.z + a.w * b.w;
    }
    #pragma unroll
    for (int o = 16; o; o >>= 1) sum += __shfl_xor_sync(0xffffffffu, sum, o);
    if (lane == 0) S0[row] = sum;
}

__global__ void softmax_kernel(const float* __restrict__ SC,
                               float* __restrict__ S0,
                               uint32_t* __restrict__ PF)
{
    const int row = blockIdx.x;
    const float* s = SC + (size_t)row * 512;
    const int tid = threadIdx.x;
    __shared__ float redm[4], reds[4];

    float4 v = ((const float4*)s)[tid];
    float s0 = S0[row];
    float lmax = fmaxf(fmaxf(v.x, v.y), fmaxf(v.z, v.w));
    if (tid == 0) lmax = fmaxf(lmax, s0);
    #pragma unroll
    for (int o = 16; o; o >>= 1)
        lmax = fmaxf(lmax, __shfl_xor_sync(0xffffffffu, lmax, o));
    if ((tid & 31) == 0) redm[tid >> 5] = lmax;
    __syncthreads();
    float m = fmaxf(fmaxf(redm[0], redm[1]), fmaxf(redm[2], redm[3]));

    v.x = expf(v.x - m); v.y = expf(v.y - m);
    v.z = expf(v.z - m); v.w = expf(v.w - m);
    float e0 = expf(s0 - m);
    float lsum = v.x + v.y + v.z + v.w + ((tid == 0) ? e0 : 0.f);
    #pragma unroll
    for (int o = 16; o; o >>= 1) lsum += __shfl_xor_sync(0xffffffffu, lsum, o);
    if ((tid & 31) == 0) reds[tid >> 5] = lsum;
    __syncthreads();
    float inv = 1.f / (reds[0] + reds[1] + reds[2] + reds[3]);

    uint32_t h[2], l[2];
    split2(v.x * inv, v.y * inv, h[0], l[0]);
    split2(v.z * inv, v.w * inv, h[1], l[1]);

    const int m16 = row >> 4, gid = row & 7, mhalf = (row >> 3) & 1;
    #pragma unroll
    for (int qq = 0; qq < 2; qq++) {
        int kp = 2 * tid + qq;
        int kc = kp >> 3, tg = kp & 3, khalf = (kp >> 2) & 1;
        int lane = gid * 4 + tg, comp = mhalf + 2 * khalf;
        size_t gb = (size_t)kc * (BS / 16) + m16;
        PF[(gb * 64 + lane) * 4 + comp]      = h[qq];
        PF[(gb * 64 + 32 + lane) * 4 + comp] = l[qq];
    }
    if (tid == 0) S0[row] = e0 * inv;
}

// ---------------------------------------------------------------------------
extern "C" void kernel_launch(void* const* d_in, const int* in_sizes, int n_in,
                              void* d_out, int out_size)
{
    const float* hs  = (const float*)d_in[0];
    const float* ext = (const float*)d_in[1];
    const float* Wq  = (const float*)d_in[2];
    const float* bq  = (const float*)d_in[3];
    const float* Wk  = (const float*)d_in[4];
    const float* bk  = (const float*)d_in[5];
    const float* Wv  = (const float*)d_in[6];
    const float* bv  = (const float*)d_in[7];
    float* out = (float*)d_out;

    float *q, *kt, *vt, *ve, *sc, *s0;
    uint4 *hsF, *exF, *qF, *pF, *wF, *keF, *veF;
    cudaGetSymbolAddress((void**)&q,   g_q);
    cudaGetSymbolAddress((void**)&kt,  g_kt);
    cudaGetSymbolAddress((void**)&vt,  g_vt);
    cudaGetSymbolAddress((void**)&ve,  g_ve);
    cudaGetSymbolAddress((void**)&sc,  g_sc);
    cudaGetSymbolAddress((void**)&s0,  g_s0);
    cudaGetSymbolAddress((void**)&hsF, g_hsF);
    cudaGetSymbolAddress((void**)&exF, g_exF);
    cudaGetSymbolAddress((void**)&qF,  g_qF);
    cudaGetSymbolAddress((void**)&pF,  g_pF);
    cudaGetSymbolAddress((void**)&wF,  g_wF);
    cudaGetSymbolAddress((void**)&keF, g_keF);
    cudaGetSymbolAddress((void**)&veF, g_veF);

    cudaFuncSetAttribute(gemm_proj_all,
        cudaFuncAttributeMaxDynamicSharedMemorySize, SMEM_GEMM);
    cudaFuncSetAttribute(gemm_scores,
        cudaFuncAttributeMaxDynamicSharedMemorySize, SMEM_S);
    cudaFuncSetAttribute(gemm_ctx,
        cudaFuncAttributeMaxDynamicSharedMemorySize, SMEM_GEMM);

    // All input conversions, one launch
    conv_all<<<3328, 256>>>(hs, ext, Wq, Wk, Wv, hsF, exF, wF);

    // All 5 projections, one launch (qF/keF emitted in-epilogue)
    gemm_proj_all<<<dim3(8, 80, 3), 256, SMEM_GEMM>>>(
        hsF, exF, wF, bq, bk, bv, q, kt, vt, ve, qF, keF);

    // ve -> B-frag for ctx
    conv_B<<<dim3(Hh / 64, BE / 64), 256>>>(ve, veF, BE, Hh, 1.0f);

    // Scores (64x128 tiles, 512 CTAs)
    self_dot_kernel<<<BS / 8, 256>>>(q, kt, s0);
    gemm_scores<<<dim3(4, Ss / 64, Bb), 256, SMEM_S>>>(qF, keF, sc);

    // Softmax (emits fragment-major probs)
    softmax_kernel<<<BS, 128>>>(sc, s0, (uint32_t*)pF);

    // Context
    gemm_ctx<<<dim3(8, Ss / 128, Bb), 256, SMEM_GEMM>>>(pF, s0, veF, vt, out);
}